// round 1
// baseline (speedup 1.0000x reference)
#include <cuda_runtime.h>
#include <math.h>

#define B_    64
#define C_    384
#define N_    256      // tokens = H*W
#define NT    (B_*N_)  // 16384
#define INNER 256
#define HID   1536
#define HEADS 8
#define DHEAD 32

// ---------------- scratch (no allocations allowed) ----------------
__device__ float g_t[NT*C_];        // [B, n, C] transposed input
__device__ float g_a[NT*C_];        // LN1 output
__device__ float g_f[NT*C_];        // LN2 output
__device__ float g_qkv[NT*3*INNER]; // [B*n, 768]
__device__ float g_o[NT*INNER];     // attention output [B*n, 256]
__device__ float g_attn[NT*C_];     // attn projection output
__device__ float g_h[NT*HID];       // MLP hidden
__device__ float g_y[NT*C_];        // final [B, n, C] before transpose

// ---------------- transpose: in [B, R, Cc] -> out [B, Cc, R] ----------------
template<int R, int Cc>
__global__ void transpose_kernel(const float* __restrict__ in, float* __restrict__ out) {
    __shared__ float tile[32][33];
    int b  = blockIdx.z;
    int c0 = blockIdx.x * 32;
    int r0 = blockIdx.y * 32;
    const float* inb  = in  + (size_t)b * R * Cc;
    float*       outb = out + (size_t)b * R * Cc;
    #pragma unroll
    for (int i = threadIdx.y; i < 32; i += 8)
        tile[i][threadIdx.x] = inb[(size_t)(r0 + i) * Cc + c0 + threadIdx.x];
    __syncthreads();
    #pragma unroll
    for (int i = threadIdx.y; i < 32; i += 8)
        outb[(size_t)(c0 + i) * R + r0 + threadIdx.x] = tile[threadIdx.x][i];
}

// ---------------- dual layernorm: reads g_t, writes g_a (ln1) and g_f (ln2) ----------------
__global__ void __launch_bounds__(128) ln_dual_kernel(
    const float* __restrict__ g1, const float* __restrict__ b1,
    const float* __restrict__ g2, const float* __restrict__ b2) {
    int token = blockIdx.x;
    const float* tp = g_t + (size_t)token * C_;
    int tid = threadIdx.x;
    float v[3];
    float s = 0.f, ss = 0.f;
    #pragma unroll
    for (int i = 0; i < 3; i++) {
        v[i] = tp[tid + i * 128];
        s += v[i]; ss += v[i] * v[i];
    }
    #pragma unroll
    for (int o = 16; o > 0; o >>= 1) {
        s  += __shfl_down_sync(0xffffffffu, s,  o);
        ss += __shfl_down_sync(0xffffffffu, ss, o);
    }
    __shared__ float rs[4], rss[4];
    __shared__ float s_mean, s_rstd;
    if ((tid & 31) == 0) { rs[tid >> 5] = s; rss[tid >> 5] = ss; }
    __syncthreads();
    if (tid == 0) {
        float S  = rs[0] + rs[1] + rs[2] + rs[3];
        float SS = rss[0] + rss[1] + rss[2] + rss[3];
        float mean = S / (float)C_;
        float var  = SS / (float)C_ - mean * mean;
        s_mean = mean;
        s_rstd = rsqrtf(var + 1e-5f);
    }
    __syncthreads();
    float mean = s_mean, rstd = s_rstd;
    #pragma unroll
    for (int i = 0; i < 3; i++) {
        int c = tid + i * 128;
        float xn = (v[i] - mean) * rstd;
        g_a[(size_t)token * C_ + c] = xn * g1[c] + b1[c];
        g_f[(size_t)token * C_ + c] = xn * g2[c] + b2[c];
    }
}

// ---------------- SGEMM: C[M,N] = A[M,K] @ B[K,N] (+ epilogue) ----------------
// EPI: 0 none, 1 +bias, 2 gelu(+bias), 3 +bias + r1 + r2 (residuals, same [M,N] layout)
template<int EPI>
__global__ void __launch_bounds__(256) sgemm_kernel(
    const float* __restrict__ A, const float* __restrict__ Bm, float* __restrict__ Cm,
    int M, int N, int K,
    const float* __restrict__ bias,
    const float* __restrict__ r1, const float* __restrict__ r2) {
    const int BM = 128, BN = 128, BK = 16;
    __shared__ float As[BK][BM];
    __shared__ float Bs[BK][BN];
    int bm = blockIdx.y * BM, bn = blockIdx.x * BN;
    int tid = threadIdx.x;
    int tr = (tid / 16) * 8;
    int tc = (tid % 16) * 8;
    float acc[8][8] = {};

    for (int k0 = 0; k0 < K; k0 += BK) {
        // load A tile (128x16) : 512 float4, 2 per thread, store transposed
        #pragma unroll
        for (int l = 0; l < 2; l++) {
            int id = tid + l * 256;
            int r = id >> 2, c4 = (id & 3) * 4;
            float4 av = *(const float4*)(A + (size_t)(bm + r) * K + k0 + c4);
            As[c4 + 0][r] = av.x; As[c4 + 1][r] = av.y;
            As[c4 + 2][r] = av.z; As[c4 + 3][r] = av.w;
        }
        // load B tile (16x128) : 512 float4, 2 per thread
        #pragma unroll
        for (int l = 0; l < 2; l++) {
            int id = tid + l * 256;
            int r = id >> 5, c4 = (id & 31) * 4;
            *(float4*)(&Bs[r][c4]) = *(const float4*)(Bm + (size_t)(k0 + r) * N + bn + c4);
        }
        __syncthreads();
        #pragma unroll
        for (int k = 0; k < BK; k++) {
            float4 a0 = *(const float4*)(&As[k][tr]);
            float4 a1 = *(const float4*)(&As[k][tr + 4]);
            float4 b0 = *(const float4*)(&Bs[k][tc]);
            float4 b1 = *(const float4*)(&Bs[k][tc + 4]);
            float ar[8] = {a0.x, a0.y, a0.z, a0.w, a1.x, a1.y, a1.z, a1.w};
            float br[8] = {b0.x, b0.y, b0.z, b0.w, b1.x, b1.y, b1.z, b1.w};
            #pragma unroll
            for (int i = 0; i < 8; i++)
                #pragma unroll
                for (int j = 0; j < 8; j++)
                    acc[i][j] += ar[i] * br[j];
        }
        __syncthreads();
    }

    #pragma unroll
    for (int i = 0; i < 8; i++) {
        int row = bm + tr + i;
        #pragma unroll
        for (int j = 0; j < 8; j++) {
            int col = bn + tc + j;
            float val = acc[i][j];
            if (EPI >= 1) val += bias[col];
            if (EPI == 2) val = 0.5f * val * (1.0f + erff(val * 0.70710678118654752f));
            if (EPI == 3) {
                size_t idx = (size_t)row * N + col;
                val += r1[idx] + r2[idx];
            }
            Cm[(size_t)row * N + col] = val;
        }
    }
}

// ---------------- attention: one block per (batch, head) ----------------
__global__ void __launch_bounds__(256) attn_kernel(const float* __restrict__ bias_table) {
    extern __shared__ float sm[];
    float* ks = sm;                      // 256*32
    float* vs = sm + N_ * DHEAD;         // 256*32
    float* bt = sm + 2 * N_ * DHEAD;     // 961 (per-head bias column)
    int b = blockIdx.x >> 3;
    int h = blockIdx.x & 7;
    int tid = threadIdx.x;
    const float* qkvb = g_qkv + (size_t)b * N_ * (3 * INNER);

    for (int idx = tid; idx < N_ * DHEAD; idx += 256) {
        int j = idx >> 5, d = idx & 31;
        ks[idx] = qkvb[(size_t)j * 768 + INNER     + h * DHEAD + d];
        vs[idx] = qkvb[(size_t)j * 768 + 2 * INNER + h * DHEAD + d];
    }
    for (int t2 = tid; t2 < 961; t2 += 256)
        bt[t2] = bias_table[t2 * HEADS + h];
    __syncthreads();

    int i = tid;                          // query index
    float q[DHEAD];
    const float* qp = qkvb + (size_t)i * 768 + h * DHEAD;
    #pragma unroll
    for (int d = 0; d < DHEAD; d++) q[d] = qp[d] * 0.17677669529663689f; // 1/sqrt(32)
    int yi = i >> 4, xi = i & 15;

    // pass 1: online max + sum
    float m = -1e30f, sum = 0.f;
    for (int j = 0; j < N_; j++) {
        const float4* k4 = (const float4*)(ks + j * DHEAD);
        float s = 0.f;
        #pragma unroll
        for (int d4 = 0; d4 < 8; d4++) {
            float4 kv = k4[d4];
            s += q[d4*4+0]*kv.x + q[d4*4+1]*kv.y + q[d4*4+2]*kv.z + q[d4*4+3]*kv.w;
        }
        int yj = j >> 4, xj = j & 15;
        s += bt[(yi - yj + 15) * 31 + (xi - xj + 15)];
        float mn = fmaxf(m, s);
        sum = sum * __expf(m - mn) + __expf(s - mn);
        m = mn;
    }
    float inv = 1.0f / sum;

    // pass 2: recompute scores, accumulate output
    float acc[DHEAD] = {};
    for (int j = 0; j < N_; j++) {
        const float4* k4 = (const float4*)(ks + j * DHEAD);
        float s = 0.f;
        #pragma unroll
        for (int d4 = 0; d4 < 8; d4++) {
            float4 kv = k4[d4];
            s += q[d4*4+0]*kv.x + q[d4*4+1]*kv.y + q[d4*4+2]*kv.z + q[d4*4+3]*kv.w;
        }
        int yj = j >> 4, xj = j & 15;
        s += bt[(yi - yj + 15) * 31 + (xi - xj + 15)];
        float p = __expf(s - m) * inv;
        const float4* v4 = (const float4*)(vs + j * DHEAD);
        #pragma unroll
        for (int d4 = 0; d4 < 8; d4++) {
            float4 vv = v4[d4];
            acc[d4*4+0] += p * vv.x; acc[d4*4+1] += p * vv.y;
            acc[d4*4+2] += p * vv.z; acc[d4*4+3] += p * vv.w;
        }
    }
    float* op = g_o + ((size_t)(b * N_ + i)) * INNER + h * DHEAD;
    #pragma unroll
    for (int d = 0; d < DHEAD; d++) op[d] = acc[d];
}

// ---------------- launch ----------------
extern "C" void kernel_launch(void* const* d_in, const int* in_sizes, int n_in,
                              void* d_out, int out_size) {
    const float* x      = (const float*)d_in[0];
    const float* ln1_g  = (const float*)d_in[1];
    const float* ln1_b  = (const float*)d_in[2];
    const float* w_qkv  = (const float*)d_in[3];
    const float* btab   = (const float*)d_in[4];
    const float* w_out  = (const float*)d_in[5];
    const float* b_out  = (const float*)d_in[6];
    const float* ln2_g  = (const float*)d_in[7];
    const float* ln2_b  = (const float*)d_in[8];
    const float* w_ff1  = (const float*)d_in[9];
    const float* b_ff1  = (const float*)d_in[10];
    const float* w_ff2  = (const float*)d_in[11];
    const float* b_ff2  = (const float*)d_in[12];
    float* out = (float*)d_out;

    float *p_t, *p_a, *p_f, *p_qkv, *p_o, *p_attn, *p_h, *p_y;
    cudaGetSymbolAddress((void**)&p_t,    g_t);
    cudaGetSymbolAddress((void**)&p_a,    g_a);
    cudaGetSymbolAddress((void**)&p_f,    g_f);
    cudaGetSymbolAddress((void**)&p_qkv,  g_qkv);
    cudaGetSymbolAddress((void**)&p_o,    g_o);
    cudaGetSymbolAddress((void**)&p_attn, g_attn);
    cudaGetSymbolAddress((void**)&p_h,    g_h);
    cudaGetSymbolAddress((void**)&p_y,    g_y);

    dim3 tb(32, 8);

    // 1. x [B, C, n] -> t [B, n, C]
    transpose_kernel<C_, N_><<<dim3(N_/32, C_/32, B_), tb>>>(x, p_t);

    // 2. dual layernorm
    ln_dual_kernel<<<NT, 128>>>(ln1_g, ln1_b, ln2_g, ln2_b);

    // 3. qkv = a @ w_qkv   [16384, 768]
    sgemm_kernel<0><<<dim3((3*INNER)/128, NT/128), 256>>>(
        p_a, w_qkv, p_qkv, NT, 3*INNER, C_, nullptr, nullptr, nullptr);

    // 4. attention
    int smem_bytes = (2 * N_ * DHEAD + 961) * (int)sizeof(float);
    cudaFuncSetAttribute(attn_kernel, cudaFuncAttributeMaxDynamicSharedMemorySize, smem_bytes);
    attn_kernel<<<B_ * HEADS, 256, smem_bytes>>>(btab);

    // 5. attn_out = o @ w_out + b_out   [16384, 384]
    sgemm_kernel<1><<<dim3(C_/128, NT/128), 256>>>(
        p_o, w_out, p_attn, NT, C_, INNER, b_out, nullptr, nullptr);

    // 6. h = gelu(f @ w_ff1 + b_ff1)   [16384, 1536]
    sgemm_kernel<2><<<dim3(HID/128, NT/128), 256>>>(
        p_f, w_ff1, p_h, NT, HID, C_, b_ff1, nullptr, nullptr);

    // 7. y = h @ w_ff2 + b_ff2 + t + attn_out   [16384, 384]
    sgemm_kernel<3><<<dim3(C_/128, NT/128), 256>>>(
        p_h, w_ff2, p_y, NT, C_, HID, b_ff2, p_t, p_attn);

    // 8. y [B, n, C] -> out [B, C, n]
    transpose_kernel<N_, C_><<<dim3(C_/32, N_/32, B_), tb>>>(p_y, out);
}

// round 3
// speedup vs baseline: 2.6049x; 2.6049x over previous
#include <cuda_runtime.h>
#include <math.h>

#define B_    64
#define C_    384
#define N_    256      // tokens = H*W
#define NT    (B_*N_)  // 16384
#define INNER 256
#define HID   1536
#define HEADS 8
#define DHEAD 32

// ---------------- scratch (no allocations allowed) ----------------
__device__ float g_t[NT*C_];        // [B, n, C] transposed input
__device__ float g_a[NT*C_];        // LN1 output
__device__ float g_f[NT*C_];        // LN2 output
__device__ float g_qkv[NT*3*INNER]; // [B*n, 768]
__device__ float g_o[NT*INNER];     // attention output [B*n, 256]
__device__ float g_attn[NT*C_];     // attn projection output
__device__ float g_h[NT*HID];       // MLP hidden
__device__ float g_y[NT*C_];        // final [B, n, C] before transpose

__device__ __forceinline__ unsigned f2tf(float x) {
    unsigned r; asm("cvt.rna.tf32.f32 %0, %1;" : "=r"(r) : "f"(x)); return r;
}

// ---------------- transpose: in [B, R, Cc] -> out [B, Cc, R] ----------------
template<int R, int Cc>
__global__ void transpose_kernel(const float* __restrict__ in, float* __restrict__ out) {
    __shared__ float tile[32][33];
    int b  = blockIdx.z;
    int c0 = blockIdx.x * 32;
    int r0 = blockIdx.y * 32;
    const float* inb  = in  + (size_t)b * R * Cc;
    float*       outb = out + (size_t)b * R * Cc;
    #pragma unroll
    for (int i = threadIdx.y; i < 32; i += 8)
        tile[i][threadIdx.x] = inb[(size_t)(r0 + i) * Cc + c0 + threadIdx.x];
    __syncthreads();
    #pragma unroll
    for (int i = threadIdx.y; i < 32; i += 8)
        outb[(size_t)(c0 + i) * R + r0 + threadIdx.x] = tile[threadIdx.x][i];
}

// ---------------- dual layernorm ----------------
__global__ void __launch_bounds__(128) ln_dual_kernel(
    const float* __restrict__ g1, const float* __restrict__ b1,
    const float* __restrict__ g2, const float* __restrict__ b2) {
    int token = blockIdx.x;
    const float* tp = g_t + (size_t)token * C_;
    int tid = threadIdx.x;
    float v[3];
    float s = 0.f, ss = 0.f;
    #pragma unroll
    for (int i = 0; i < 3; i++) {
        v[i] = tp[tid + i * 128];
        s += v[i]; ss += v[i] * v[i];
    }
    #pragma unroll
    for (int o = 16; o > 0; o >>= 1) {
        s  += __shfl_down_sync(0xffffffffu, s,  o);
        ss += __shfl_down_sync(0xffffffffu, ss, o);
    }
    __shared__ float rs[4], rss[4];
    __shared__ float s_mean, s_rstd;
    if ((tid & 31) == 0) { rs[tid >> 5] = s; rss[tid >> 5] = ss; }
    __syncthreads();
    if (tid == 0) {
        float S  = rs[0] + rs[1] + rs[2] + rs[3];
        float SS = rss[0] + rss[1] + rss[2] + rss[3];
        float mean = S / (float)C_;
        float var  = SS / (float)C_ - mean * mean;
        s_mean = mean;
        s_rstd = rsqrtf(var + 1e-5f);
    }
    __syncthreads();
    float mean = s_mean, rstd = s_rstd;
    #pragma unroll
    for (int i = 0; i < 3; i++) {
        int c = tid + i * 128;
        float xn = (v[i] - mean) * rstd;
        g_a[(size_t)token * C_ + c] = xn * g1[c] + b1[c];
        g_f[(size_t)token * C_ + c] = xn * g2[c] + b2[c];
    }
}

// ---------------- tf32 tensor-core GEMM: C[M,N] = A[M,K] @ B[K,N] (+ epilogue) ----------------
// EPI: 0 none, 1 +bias, 2 gelu(+bias), 3 +bias + r1 + r2
// Block tile 128x128, BK=32, 128 threads (4 warps, each 64x64 warp tile of m16n8k8 mmas)
#define SA 36
#define SB 136
template<int EPI>
__global__ void __launch_bounds__(128, 2) mma_gemm(
    const float* __restrict__ A, const float* __restrict__ Bm, float* __restrict__ Cm,
    int M, int N, int K,
    const float* __restrict__ bias,
    const float* __restrict__ r1, const float* __restrict__ r2) {
    __shared__ unsigned As[128 * SA];   // [m][k], stride 36 (conflict-free frag loads)
    __shared__ unsigned Bs[32 * SB];    // [k][n], stride 136

    int bm = blockIdx.y * 128, bn = blockIdx.x * 128;
    int tid  = threadIdx.x;
    int wid  = tid >> 5, lane = tid & 31;
    int g    = lane >> 2, tig = lane & 3;
    int m_off = (wid & 1) * 64;
    int n_off = (wid >> 1) * 64;

    float acc[4][8][4];
    #pragma unroll
    for (int mt = 0; mt < 4; mt++)
        #pragma unroll
        for (int nt = 0; nt < 8; nt++)
            #pragma unroll
            for (int c = 0; c < 4; c++) acc[mt][nt][c] = 0.f;

    int ar  = tid >> 3;          // 0..15 (row within A tile, +16*l)
    int ac4 = (tid & 7) * 4;     // k offset
    int bk  = tid >> 5;          // 0..3 (row within B tile, +4*l)
    int bn4 = (tid & 31) * 4;    // n offset

    for (int k0 = 0; k0 < K; k0 += 32) {
        __syncthreads();
        // A tile: 128x32, coalesced float4 along K, tf32-convert, STS.128
        #pragma unroll
        for (int l = 0; l < 8; l++) {
            int r = ar + l * 16;
            float4 v = *(const float4*)(A + (size_t)(bm + r) * K + k0 + ac4);
            uint4 s4 = make_uint4(f2tf(v.x), f2tf(v.y), f2tf(v.z), f2tf(v.w));
            *(uint4*)&As[r * SA + ac4] = s4;
        }
        // B tile: 32x128, coalesced float4 along N, tf32-convert, STS.128
        #pragma unroll
        for (int l = 0; l < 8; l++) {
            int r = bk + l * 4;
            float4 v = *(const float4*)(Bm + (size_t)(k0 + r) * N + bn + bn4);
            uint4 s4 = make_uint4(f2tf(v.x), f2tf(v.y), f2tf(v.z), f2tf(v.w));
            *(uint4*)&Bs[r * SB + bn4] = s4;
        }
        __syncthreads();

        #pragma unroll
        for (int kk = 0; kk < 4; kk++) {
            unsigned bfr[8][2];
            #pragma unroll
            for (int nt = 0; nt < 8; nt++) {
                int n = n_off + nt * 8 + g;
                bfr[nt][0] = Bs[(kk * 8 + tig)     * SB + n];
                bfr[nt][1] = Bs[(kk * 8 + tig + 4) * SB + n];
            }
            #pragma unroll
            for (int mt = 0; mt < 4; mt++) {
                int mrow = m_off + mt * 16 + g;
                unsigned a0 = As[(mrow)     * SA + kk * 8 + tig];
                unsigned a1 = As[(mrow + 8) * SA + kk * 8 + tig];
                unsigned a2 = As[(mrow)     * SA + kk * 8 + tig + 4];
                unsigned a3 = As[(mrow + 8) * SA + kk * 8 + tig + 4];
                #pragma unroll
                for (int nt = 0; nt < 8; nt++) {
                    asm volatile(
                        "mma.sync.aligned.m16n8k8.row.col.f32.tf32.tf32.f32 "
                        "{%0,%1,%2,%3}, {%4,%5,%6,%7}, {%8,%9}, {%0,%1,%2,%3};"
                        : "+f"(acc[mt][nt][0]), "+f"(acc[mt][nt][1]),
                          "+f"(acc[mt][nt][2]), "+f"(acc[mt][nt][3])
                        : "r"(a0), "r"(a1), "r"(a2), "r"(a3),
                          "r"(bfr[nt][0]), "r"(bfr[nt][1]));
                }
            }
        }
    }

    // epilogue
    #pragma unroll
    for (int mt = 0; mt < 4; mt++) {
        int row0 = bm + m_off + mt * 16 + g;
        #pragma unroll
        for (int nt = 0; nt < 8; nt++) {
            int col = bn + n_off + nt * 8 + 2 * tig;
            #pragma unroll
            for (int half = 0; half < 2; half++) {
                int row = row0 + half * 8;
                float v0 = acc[mt][nt][half * 2 + 0];
                float v1 = acc[mt][nt][half * 2 + 1];
                if (EPI >= 1) { v0 += bias[col]; v1 += bias[col + 1]; }
                if (EPI == 2) {
                    v0 = 0.5f * v0 * (1.0f + erff(v0 * 0.70710678118654752f));
                    v1 = 0.5f * v1 * (1.0f + erff(v1 * 0.70710678118654752f));
                }
                size_t idx = (size_t)row * N + col;
                if (EPI == 3) {
                    v0 += r1[idx] + r2[idx];
                    v1 += r1[idx + 1] + r2[idx + 1];
                }
                *(float2*)(Cm + idx) = make_float2(v0, v1);
            }
        }
    }
}

// ---------------- attention: single-pass online softmax, one block per (batch, head) ----------------
__global__ void __launch_bounds__(256) attn_kernel(const float* __restrict__ bias_table) {
    extern __shared__ float sm[];
    float* ks = sm;                      // 256*32
    float* vs = sm + N_ * DHEAD;         // 256*32
    float* bt = sm + 2 * N_ * DHEAD;     // 961 per-head bias column
    int b = blockIdx.x >> 3;
    int h = blockIdx.x & 7;
    int tid = threadIdx.x;
    const float* qkvb = g_qkv + (size_t)b * N_ * (3 * INNER);

    for (int idx = tid; idx < N_ * DHEAD; idx += 256) {
        int j = idx >> 5, d = idx & 31;
        ks[idx] = qkvb[(size_t)j * 768 + INNER     + h * DHEAD + d];
        vs[idx] = qkvb[(size_t)j * 768 + 2 * INNER + h * DHEAD + d];
    }
    for (int t2 = tid; t2 < 961; t2 += 256)
        bt[t2] = bias_table[t2 * HEADS + h];
    __syncthreads();

    int i = tid;                          // query index
    float q[DHEAD];
    const float* qp = qkvb + (size_t)i * 768 + h * DHEAD;
    #pragma unroll
    for (int d = 0; d < DHEAD; d++) q[d] = qp[d] * 0.17677669529663689f;
    int yi = i >> 4, xi = i & 15;

    float m = -1e30f, sum = 0.f;
    float acc[DHEAD];
    #pragma unroll
    for (int d = 0; d < DHEAD; d++) acc[d] = 0.f;

    for (int jt = 0; jt < 16; jt++) {
        float s[16];
        float tm = -1e30f;
        int bb = (yi - jt + 15) * 31 + xi + 15;   // bias row base (xj = jj)
        #pragma unroll
        for (int jj = 0; jj < 16; jj++) {
            int j = jt * 16 + jj;
            const float4* k4 = (const float4*)(ks + j * DHEAD);
            float d0 = 0.f;
            #pragma unroll
            for (int d4 = 0; d4 < 8; d4++) {
                float4 kv = k4[d4];
                d0 += q[d4*4+0]*kv.x + q[d4*4+1]*kv.y + q[d4*4+2]*kv.z + q[d4*4+3]*kv.w;
            }
            s[jj] = d0 + bt[bb - jj];
            tm = fmaxf(tm, s[jj]);
        }
        float mn = fmaxf(m, tm);
        float scale = __expf(m - mn);
        m = mn;
        sum *= scale;
        #pragma unroll
        for (int d = 0; d < DHEAD; d++) acc[d] *= scale;
        #pragma unroll
        for (int jj = 0; jj < 16; jj++) {
            int j = jt * 16 + jj;
            float p = __expf(s[jj] - m);
            sum += p;
            const float4* v4 = (const float4*)(vs + j * DHEAD);
            #pragma unroll
            for (int d4 = 0; d4 < 8; d4++) {
                float4 vv = v4[d4];
                acc[d4*4+0] += p * vv.x; acc[d4*4+1] += p * vv.y;
                acc[d4*4+2] += p * vv.z; acc[d4*4+3] += p * vv.w;
            }
        }
    }
    float inv = 1.0f / sum;
    float* op = g_o + ((size_t)(b * N_ + i)) * INNER + h * DHEAD;
    #pragma unroll
    for (int d = 0; d < DHEAD; d++) op[d] = acc[d] * inv;
}

// ---------------- launch ----------------
extern "C" void kernel_launch(void* const* d_in, const int* in_sizes, int n_in,
                              void* d_out, int out_size) {
    const float* x      = (const float*)d_in[0];
    const float* ln1_g  = (const float*)d_in[1];
    const float* ln1_b  = (const float*)d_in[2];
    const float* w_qkv  = (const float*)d_in[3];
    const float* btab   = (const float*)d_in[4];
    const float* w_out  = (const float*)d_in[5];
    const float* b_out  = (const float*)d_in[6];
    const float* ln2_g  = (const float*)d_in[7];
    const float* ln2_b  = (const float*)d_in[8];
    const float* w_ff1  = (const float*)d_in[9];
    const float* b_ff1  = (const float*)d_in[10];
    const float* w_ff2  = (const float*)d_in[11];
    const float* b_ff2  = (const float*)d_in[12];
    float* out = (float*)d_out;

    float *p_t, *p_a, *p_f, *p_qkv, *p_o, *p_attn, *p_h, *p_y;
    cudaGetSymbolAddress((void**)&p_t,    g_t);
    cudaGetSymbolAddress((void**)&p_a,    g_a);
    cudaGetSymbolAddress((void**)&p_f,    g_f);
    cudaGetSymbolAddress((void**)&p_qkv,  g_qkv);
    cudaGetSymbolAddress((void**)&p_o,    g_o);
    cudaGetSymbolAddress((void**)&p_attn, g_attn);
    cudaGetSymbolAddress((void**)&p_h,    g_h);
    cudaGetSymbolAddress((void**)&p_y,    g_y);

    dim3 tb(32, 8);

    // 1. x [B, C, n] -> t [B, n, C]
    transpose_kernel<C_, N_><<<dim3(N_/32, C_/32, B_), tb>>>(x, p_t);

    // 2. dual layernorm
    ln_dual_kernel<<<NT, 128>>>(ln1_g, ln1_b, ln2_g, ln2_b);

    // 3. qkv = a @ w_qkv   [16384, 768]
    mma_gemm<0><<<dim3((3*INNER)/128, NT/128), 128>>>(
        p_a, w_qkv, p_qkv, NT, 3*INNER, C_, nullptr, nullptr, nullptr);

    // 4. attention
    int smem_bytes = (2 * N_ * DHEAD + 961) * (int)sizeof(float);
    cudaFuncSetAttribute(attn_kernel, cudaFuncAttributeMaxDynamicSharedMemorySize, smem_bytes);
    attn_kernel<<<B_ * HEADS, 256, smem_bytes>>>(btab);

    // 5. attn_out = o @ w_out + b_out   [16384, 384]
    mma_gemm<1><<<dim3(C_/128, NT/128), 128>>>(
        p_o, w_out, p_attn, NT, C_, INNER, b_out, nullptr, nullptr);

    // 6. h = gelu(f @ w_ff1 + b_ff1)   [16384, 1536]
    mma_gemm<2><<<dim3(HID/128, NT/128), 128>>>(
        p_f, w_ff1, p_h, NT, HID, C_, b_ff1, nullptr, nullptr);

    // 7. y = h @ w_ff2 + b_ff2 + t + attn_out   [16384, 384]
    mma_gemm<3><<<dim3(C_/128, NT/128), 128>>>(
        p_h, w_ff2, p_y, NT, C_, HID, b_ff2, p_t, p_attn);

    // 8. y [B, n, C] -> out [B, C, n]
    transpose_kernel<N_, C_><<<dim3(C_/32, N_/32, B_), tb>>>(p_y, out);
}

// round 4
// speedup vs baseline: 3.4150x; 1.3110x over previous
#include <cuda_runtime.h>
#include <math.h>

#define B_    64
#define C_    384
#define N_    256      // tokens = H*W
#define NT    (B_*N_)  // 16384
#define INNER 256
#define HID   1536
#define HEADS 8
#define DHEAD 32

// ---------------- scratch ----------------
__device__ float g_t[NT*C_];
__device__ float g_a[NT*C_];
__device__ float g_f[NT*C_];
__device__ float g_qkv[NT*3*INNER];
__device__ float g_o[NT*INNER];
__device__ float g_attn[NT*C_];
__device__ float g_h[NT*HID];
__device__ float g_y[NT*C_];

// ---------------- cp.async helpers ----------------
__device__ __forceinline__ void cp_async16(void* dst, const void* src) {
    unsigned d = (unsigned)__cvta_generic_to_shared(dst);
    asm volatile("cp.async.cg.shared.global [%0], [%1], 16;" :: "r"(d), "l"(src));
}
__device__ __forceinline__ void cp_commit() { asm volatile("cp.async.commit_group;"); }
template<int Np> __device__ __forceinline__ void cp_wait() {
    asm volatile("cp.async.wait_group %0;" :: "n"(Np));
}

__device__ __forceinline__ void mma_tf32(float* c, unsigned a0, unsigned a1, unsigned a2, unsigned a3,
                                         unsigned b0, unsigned b1) {
    asm volatile(
        "mma.sync.aligned.m16n8k8.row.col.f32.tf32.tf32.f32 "
        "{%0,%1,%2,%3}, {%4,%5,%6,%7}, {%8,%9}, {%0,%1,%2,%3};"
        : "+f"(c[0]), "+f"(c[1]), "+f"(c[2]), "+f"(c[3])
        : "r"(a0), "r"(a1), "r"(a2), "r"(a3), "r"(b0), "r"(b1));
}

// ---------------- transpose ----------------
template<int R, int Cc>
__global__ void transpose_kernel(const float* __restrict__ in, float* __restrict__ out) {
    __shared__ float tile[32][33];
    int b  = blockIdx.z;
    int c0 = blockIdx.x * 32;
    int r0 = blockIdx.y * 32;
    const float* inb  = in  + (size_t)b * R * Cc;
    float*       outb = out + (size_t)b * R * Cc;
    #pragma unroll
    for (int i = threadIdx.y; i < 32; i += 8)
        tile[i][threadIdx.x] = inb[(size_t)(r0 + i) * Cc + c0 + threadIdx.x];
    __syncthreads();
    #pragma unroll
    for (int i = threadIdx.y; i < 32; i += 8)
        outb[(size_t)(c0 + i) * R + r0 + threadIdx.x] = tile[threadIdx.x][i];
}

// ---------------- dual layernorm ----------------
__global__ void __launch_bounds__(128) ln_dual_kernel(
    const float* __restrict__ g1, const float* __restrict__ b1,
    const float* __restrict__ g2, const float* __restrict__ b2) {
    int token = blockIdx.x;
    const float* tp = g_t + (size_t)token * C_;
    int tid = threadIdx.x;
    float v[3];
    float s = 0.f, ss = 0.f;
    #pragma unroll
    for (int i = 0; i < 3; i++) {
        v[i] = tp[tid + i * 128];
        s += v[i]; ss += v[i] * v[i];
    }
    #pragma unroll
    for (int o = 16; o > 0; o >>= 1) {
        s  += __shfl_down_sync(0xffffffffu, s,  o);
        ss += __shfl_down_sync(0xffffffffu, ss, o);
    }
    __shared__ float rs[4], rss[4];
    __shared__ float s_mean, s_rstd;
    if ((tid & 31) == 0) { rs[tid >> 5] = s; rss[tid >> 5] = ss; }
    __syncthreads();
    if (tid == 0) {
        float S  = rs[0] + rs[1] + rs[2] + rs[3];
        float SS = rss[0] + rss[1] + rss[2] + rss[3];
        float mean = S / (float)C_;
        float var  = SS / (float)C_ - mean * mean;
        s_mean = mean;
        s_rstd = rsqrtf(var + 1e-5f);
    }
    __syncthreads();
    float mean = s_mean, rstd = s_rstd;
    #pragma unroll
    for (int i = 0; i < 3; i++) {
        int c = tid + i * 128;
        float xn = (v[i] - mean) * rstd;
        g_a[(size_t)token * C_ + c] = xn * g1[c] + b1[c];
        g_f[(size_t)token * C_ + c] = xn * g2[c] + b2[c];
    }
}

// ---------------- tf32 GEMM, cp.async double-buffered ----------------
// EPI: 0 none, 1 +bias, 2 gelu(+bias), 3 +bias + r1 + r2
#define SA 36
#define SB 132
#define STAGE_W (128*SA + 32*SB)   // 8832 words per stage

template<int EPI>
__global__ void __launch_bounds__(128, 2) mma_gemm(
    const float* __restrict__ A, const float* __restrict__ Bm, float* __restrict__ Cm,
    int M, int N, int K,
    const float* __restrict__ bias,
    const float* __restrict__ r1, const float* __restrict__ r2) {
    extern __shared__ float sh[];

    int bm = blockIdx.y * 128, bn = blockIdx.x * 128;
    int tid  = threadIdx.x;
    int wid  = tid >> 5, lane = tid & 31;
    int g    = lane >> 2, tig = lane & 3;
    int m_off = (wid & 1) * 64;
    int n_off = (wid >> 1) * 64;

    float acc[4][8][4];
    #pragma unroll
    for (int mt = 0; mt < 4; mt++)
        #pragma unroll
        for (int nt = 0; nt < 8; nt++)
            #pragma unroll
            for (int c = 0; c < 4; c++) acc[mt][nt][c] = 0.f;

    int ar  = tid >> 3;          // A row base (0..15)
    int ac4 = (tid & 7) * 4;     // A k offset
    int bk  = tid >> 5;          // B row base (0..3)
    int bn4 = (tid & 31) * 4;    // B n offset

    int nIter = K >> 5;

    // prologue: stage 0
    {
        float* Ab = sh;
        float* Bb = sh + 128 * SA;
        #pragma unroll
        for (int l = 0; l < 8; l++) {
            int r = ar + l * 16;
            cp_async16(&Ab[r * SA + ac4], A + (size_t)(bm + r) * K + ac4);
        }
        #pragma unroll
        for (int l = 0; l < 8; l++) {
            int r = bk + l * 4;
            cp_async16(&Bb[r * SB + bn4], Bm + (size_t)r * N + bn + bn4);
        }
        cp_commit();
    }

    for (int it = 0; it < nIter; it++) {
        if (it + 1 < nIter) {
            int k0 = (it + 1) * 32;
            float* Ab = sh + ((it + 1) & 1) * STAGE_W;
            float* Bb = Ab + 128 * SA;
            #pragma unroll
            for (int l = 0; l < 8; l++) {
                int r = ar + l * 16;
                cp_async16(&Ab[r * SA + ac4], A + (size_t)(bm + r) * K + k0 + ac4);
            }
            #pragma unroll
            for (int l = 0; l < 8; l++) {
                int r = bk + l * 4;
                cp_async16(&Bb[r * SB + bn4], Bm + (size_t)(k0 + r) * N + bn + bn4);
            }
            cp_commit();
            cp_wait<1>();
        } else {
            cp_wait<0>();
        }
        __syncthreads();

        const float* As = sh + (it & 1) * STAGE_W;
        const float* Bs = As + 128 * SA;

        #pragma unroll
        for (int kk = 0; kk < 4; kk++) {
            unsigned bfr[8][2];
            #pragma unroll
            for (int nt = 0; nt < 8; nt++) {
                int n = n_off + nt * 8 + g;
                bfr[nt][0] = __float_as_uint(Bs[(kk * 8 + tig)     * SB + n]);
                bfr[nt][1] = __float_as_uint(Bs[(kk * 8 + tig + 4) * SB + n]);
            }
            #pragma unroll
            for (int mt = 0; mt < 4; mt++) {
                int mrow = m_off + mt * 16 + g;
                unsigned a0 = __float_as_uint(As[(mrow)     * SA + kk * 8 + tig]);
                unsigned a1 = __float_as_uint(As[(mrow + 8) * SA + kk * 8 + tig]);
                unsigned a2 = __float_as_uint(As[(mrow)     * SA + kk * 8 + tig + 4]);
                unsigned a3 = __float_as_uint(As[(mrow + 8) * SA + kk * 8 + tig + 4]);
                #pragma unroll
                for (int nt = 0; nt < 8; nt++)
                    mma_tf32(acc[mt][nt], a0, a1, a2, a3, bfr[nt][0], bfr[nt][1]);
            }
        }
        __syncthreads();
    }

    // epilogue
    #pragma unroll
    for (int mt = 0; mt < 4; mt++) {
        int row0 = bm + m_off + mt * 16 + g;
        #pragma unroll
        for (int nt = 0; nt < 8; nt++) {
            int col = bn + n_off + nt * 8 + 2 * tig;
            #pragma unroll
            for (int half = 0; half < 2; half++) {
                int row = row0 + half * 8;
                float v0 = acc[mt][nt][half * 2 + 0];
                float v1 = acc[mt][nt][half * 2 + 1];
                if (EPI >= 1) { v0 += bias[col]; v1 += bias[col + 1]; }
                if (EPI == 2) {
                    v0 = 0.5f * v0 * (1.0f + erff(v0 * 0.70710678118654752f));
                    v1 = 0.5f * v1 * (1.0f + erff(v1 * 0.70710678118654752f));
                }
                size_t idx = (size_t)row * N + col;
                if (EPI == 3) {
                    v0 += r1[idx] + r2[idx];
                    v1 += r1[idx + 1] + r2[idx + 1];
                }
                *(float2*)(Cm + idx) = make_float2(v0, v1);
            }
        }
    }
}

// ---------------- tensor-core attention ----------------
// 1 block = 1 (batch, head); 256 threads = 8 warps; warp w owns q rows [32w, 32w+32)
// smem: ks[256*36] vs[256*36] qp[18432 (Q staging -> per-warp P 32x72)] bt[961]
#define ATT_SMEM_W (256*36 + 256*36 + 18432 + 961)
__global__ void __launch_bounds__(256) attn_tc_kernel(const float* __restrict__ bias_table) {
    extern __shared__ float sm[];
    float* ks = sm;
    float* vs = ks + 256 * 36;
    float* qp = vs + 256 * 36;      // Q staging, later P buffers
    float* bt = qp + 18432;
    int b = blockIdx.x >> 3;
    int h = blockIdx.x & 7;
    int tid = threadIdx.x, w = tid >> 5, lane = tid & 31;
    int g = lane >> 2, tig = lane & 3;
    const float* qkvb = g_qkv + (size_t)b * N_ * 768;

    // stage Q (scaled), K, V into padded smem
    #pragma unroll
    for (int it = 0; it < 8; it++) {
        int idx = tid + it * 256;       // 0..2047
        int j = idx >> 3, d4 = (idx & 7) * 4;
        const float* base = qkvb + (size_t)j * 768 + h * 32 + d4;
        float4 qv = *(const float4*)(base);
        qv.x *= 0.17677669529663689f; qv.y *= 0.17677669529663689f;
        qv.z *= 0.17677669529663689f; qv.w *= 0.17677669529663689f;
        *(float4*)(qp + j * 36 + d4) = qv;
        *(float4*)(ks + j * 36 + d4) = *(const float4*)(base + 256);
        *(float4*)(vs + j * 36 + d4) = *(const float4*)(base + 512);
    }
    for (int t = tid; t < 961; t += 256)
        bt[t] = bias_table[t * HEADS + h];
    __syncthreads();

    // Q fragments (warp-resident)
    int qb = w * 32;
    unsigned qa[2][4][4];
    #pragma unroll
    for (int mt = 0; mt < 2; mt++)
        #pragma unroll
        for (int kk = 0; kk < 4; kk++) {
            int r0 = (qb + mt * 16 + g) * 36;
            int r1 = r0 + 8 * 36;
            qa[mt][kk][0] = __float_as_uint(qp[r0 + kk * 8 + tig]);
            qa[mt][kk][1] = __float_as_uint(qp[r1 + kk * 8 + tig]);
            qa[mt][kk][2] = __float_as_uint(qp[r0 + kk * 8 + tig + 4]);
            qa[mt][kk][3] = __float_as_uint(qp[r1 + kk * 8 + tig + 4]);
        }
    __syncthreads();   // qp now free to become P space

    float* ps = qp + w * 2304;    // 32 rows x 72

    float mrow[2][2], lrow[2][2];
    #pragma unroll
    for (int mt = 0; mt < 2; mt++) { mrow[mt][0] = mrow[mt][1] = -1e30f; lrow[mt][0] = lrow[mt][1] = 0.f; }
    float acc[2][4][4];
    #pragma unroll
    for (int mt = 0; mt < 2; mt++)
        #pragma unroll
        for (int nt = 0; nt < 4; nt++)
            #pragma unroll
            for (int c = 0; c < 4; c++) acc[mt][nt][c] = 0.f;

    int yi[2][2], xi[2][2];
    #pragma unroll
    for (int mt = 0; mt < 2; mt++)
        #pragma unroll
        for (int hf = 0; hf < 2; hf++) {
            int i = qb + mt * 16 + g + 8 * hf;
            yi[mt][hf] = i >> 4; xi[mt][hf] = i & 15;
        }

    for (int jt = 0; jt < 4; jt++) {
        int jb = jt * 64;
        float s[2][8][4];
        #pragma unroll
        for (int mt = 0; mt < 2; mt++)
            #pragma unroll
            for (int nj = 0; nj < 8; nj++)
                #pragma unroll
                for (int c = 0; c < 4; c++) s[mt][nj][c] = 0.f;

        // S = Q K^T
        #pragma unroll
        for (int kk = 0; kk < 4; kk++) {
            unsigned bf[8][2];
            #pragma unroll
            for (int nj = 0; nj < 8; nj++) {
                int jr = (jb + nj * 8 + g) * 36;
                bf[nj][0] = __float_as_uint(ks[jr + kk * 8 + tig]);
                bf[nj][1] = __float_as_uint(ks[jr + kk * 8 + tig + 4]);
            }
            #pragma unroll
            for (int mt = 0; mt < 2; mt++)
                #pragma unroll
                for (int nj = 0; nj < 8; nj++)
                    mma_tf32(s[mt][nj], qa[mt][kk][0], qa[mt][kk][1], qa[mt][kk][2], qa[mt][kk][3],
                             bf[nj][0], bf[nj][1]);
        }

        // bias add
        #pragma unroll
        for (int mt = 0; mt < 2; mt++)
            #pragma unroll
            for (int nj = 0; nj < 8; nj++)
                #pragma unroll
                for (int c = 0; c < 4; c++) {
                    int hf = c >> 1;
                    int j = jb + nj * 8 + 2 * tig + (c & 1);
                    int bidx = (yi[mt][hf] - (j >> 4) + 15) * 31 + (xi[mt][hf] - (j & 15) + 15);
                    s[mt][nj][c] += bt[bidx];
                }

        // online softmax update
        #pragma unroll
        for (int mt = 0; mt < 2; mt++)
            #pragma unroll
            for (int hf = 0; hf < 2; hf++) {
                float tm = -1e30f;
                #pragma unroll
                for (int nj = 0; nj < 8; nj++)
                    tm = fmaxf(tm, fmaxf(s[mt][nj][hf*2], s[mt][nj][hf*2+1]));
                tm = fmaxf(tm, __shfl_xor_sync(0xffffffffu, tm, 1));
                tm = fmaxf(tm, __shfl_xor_sync(0xffffffffu, tm, 2));
                float nm = fmaxf(mrow[mt][hf], tm);
                float scale = __expf(mrow[mt][hf] - nm);
                mrow[mt][hf] = nm;
                float rs = 0.f;
                #pragma unroll
                for (int nj = 0; nj < 8; nj++) {
                    float p0 = __expf(s[mt][nj][hf*2]   - nm);
                    float p1 = __expf(s[mt][nj][hf*2+1] - nm);
                    s[mt][nj][hf*2] = p0; s[mt][nj][hf*2+1] = p1;
                    rs += p0 + p1;
                }
                rs += __shfl_xor_sync(0xffffffffu, rs, 1);
                rs += __shfl_xor_sync(0xffffffffu, rs, 2);
                lrow[mt][hf] = lrow[mt][hf] * scale + rs;
                #pragma unroll
                for (int nt = 0; nt < 4; nt++) {
                    acc[mt][nt][hf*2]   *= scale;
                    acc[mt][nt][hf*2+1] *= scale;
                }
            }

        // write P to smem (per-warp buffer)
        #pragma unroll
        for (int mt = 0; mt < 2; mt++)
            #pragma unroll
            for (int nj = 0; nj < 8; nj++) {
                int r0 = (mt * 16 + g) * 72 + nj * 8 + 2 * tig;
                *(float2*)(ps + r0)          = make_float2(s[mt][nj][0], s[mt][nj][1]);
                *(float2*)(ps + r0 + 8 * 72) = make_float2(s[mt][nj][2], s[mt][nj][3]);
            }
        __syncwarp();

        // O += P V
        #pragma unroll
        for (int kk2 = 0; kk2 < 8; kk2++) {
            unsigned pa[2][4];
            #pragma unroll
            for (int mt = 0; mt < 2; mt++) {
                int r0 = (mt * 16 + g) * 72;
                int r1 = r0 + 8 * 72;
                pa[mt][0] = __float_as_uint(ps[r0 + kk2 * 8 + tig]);
                pa[mt][1] = __float_as_uint(ps[r1 + kk2 * 8 + tig]);
                pa[mt][2] = __float_as_uint(ps[r0 + kk2 * 8 + tig + 4]);
                pa[mt][3] = __float_as_uint(ps[r1 + kk2 * 8 + tig + 4]);
            }
            unsigned vb[4][2];
            #pragma unroll
            for (int nt = 0; nt < 4; nt++) {
                vb[nt][0] = __float_as_uint(vs[(jb + kk2 * 8 + tig)     * 36 + nt * 8 + g]);
                vb[nt][1] = __float_as_uint(vs[(jb + kk2 * 8 + tig + 4) * 36 + nt * 8 + g]);
            }
            #pragma unroll
            for (int mt = 0; mt < 2; mt++)
                #pragma unroll
                for (int nt = 0; nt < 4; nt++)
                    mma_tf32(acc[mt][nt], pa[mt][0], pa[mt][1], pa[mt][2], pa[mt][3],
                             vb[nt][0], vb[nt][1]);
        }
        __syncwarp();  // before next jt overwrites ps
    }

    // normalize + store
    #pragma unroll
    for (int mt = 0; mt < 2; mt++) {
        float inv0 = 1.0f / lrow[mt][0];
        float inv1 = 1.0f / lrow[mt][1];
        int tok0 = b * N_ + qb + mt * 16 + g;
        int tok1 = tok0 + 8;
        #pragma unroll
        for (int nt = 0; nt < 4; nt++) {
            int col = h * 32 + nt * 8 + 2 * tig;
            *(float2*)(g_o + (size_t)tok0 * INNER + col) =
                make_float2(acc[mt][nt][0] * inv0, acc[mt][nt][1] * inv0);
            *(float2*)(g_o + (size_t)tok1 * INNER + col) =
                make_float2(acc[mt][nt][2] * inv1, acc[mt][nt][3] * inv1);
        }
    }
}

// ---------------- launch ----------------
extern "C" void kernel_launch(void* const* d_in, const int* in_sizes, int n_in,
                              void* d_out, int out_size) {
    const float* x      = (const float*)d_in[0];
    const float* ln1_g  = (const float*)d_in[1];
    const float* ln1_b  = (const float*)d_in[2];
    const float* w_qkv  = (const float*)d_in[3];
    const float* btab   = (const float*)d_in[4];
    const float* w_out  = (const float*)d_in[5];
    const float* b_out  = (const float*)d_in[6];
    const float* ln2_g  = (const float*)d_in[7];
    const float* ln2_b  = (const float*)d_in[8];
    const float* w_ff1  = (const float*)d_in[9];
    const float* b_ff1  = (const float*)d_in[10];
    const float* w_ff2  = (const float*)d_in[11];
    const float* b_ff2  = (const float*)d_in[12];
    float* out = (float*)d_out;

    float *p_t, *p_a, *p_f, *p_qkv, *p_o, *p_attn, *p_h, *p_y;
    cudaGetSymbolAddress((void**)&p_t,    g_t);
    cudaGetSymbolAddress((void**)&p_a,    g_a);
    cudaGetSymbolAddress((void**)&p_f,    g_f);
    cudaGetSymbolAddress((void**)&p_qkv,  g_qkv);
    cudaGetSymbolAddress((void**)&p_o,    g_o);
    cudaGetSymbolAddress((void**)&p_attn, g_attn);
    cudaGetSymbolAddress((void**)&p_h,    g_h);
    cudaGetSymbolAddress((void**)&p_y,    g_y);

    int gemm_smem = STAGE_W * 2 * (int)sizeof(float);
    cudaFuncSetAttribute(mma_gemm<0>, cudaFuncAttributeMaxDynamicSharedMemorySize, gemm_smem);
    cudaFuncSetAttribute(mma_gemm<1>, cudaFuncAttributeMaxDynamicSharedMemorySize, gemm_smem);
    cudaFuncSetAttribute(mma_gemm<2>, cudaFuncAttributeMaxDynamicSharedMemorySize, gemm_smem);
    cudaFuncSetAttribute(mma_gemm<3>, cudaFuncAttributeMaxDynamicSharedMemorySize, gemm_smem);
    int attn_smem = ATT_SMEM_W * (int)sizeof(float);
    cudaFuncSetAttribute(attn_tc_kernel, cudaFuncAttributeMaxDynamicSharedMemorySize, attn_smem);

    dim3 tb(32, 8);

    // 1. x [B, C, n] -> t [B, n, C]
    transpose_kernel<C_, N_><<<dim3(N_/32, C_/32, B_), tb>>>(x, p_t);

    // 2. dual layernorm
    ln_dual_kernel<<<NT, 128>>>(ln1_g, ln1_b, ln2_g, ln2_b);

    // 3. qkv = a @ w_qkv
    mma_gemm<0><<<dim3((3*INNER)/128, NT/128), 128, gemm_smem>>>(
        p_a, w_qkv, p_qkv, NT, 3*INNER, C_, nullptr, nullptr, nullptr);

    // 4. attention (tensor-core)
    attn_tc_kernel<<<B_ * HEADS, 256, attn_smem>>>(btab);

    // 5. attn_out = o @ w_out + b_out
    mma_gemm<1><<<dim3(C_/128, NT/128), 128, gemm_smem>>>(
        p_o, w_out, p_attn, NT, C_, INNER, b_out, nullptr, nullptr);

    // 6. h = gelu(f @ w_ff1 + b_ff1)
    mma_gemm<2><<<dim3(HID/128, NT/128), 128, gemm_smem>>>(
        p_f, w_ff1, p_h, NT, HID, C_, b_ff1, nullptr, nullptr);

    // 7. y = h @ w_ff2 + b_ff2 + t + attn_out
    mma_gemm<3><<<dim3(C_/128, NT/128), 128, gemm_smem>>>(
        p_h, w_ff2, p_y, NT, C_, HID, b_ff2, p_t, p_attn);

    // 8. y [B, n, C] -> out [B, C, n]
    transpose_kernel<N_, C_><<<dim3(C_/32, N_/32, B_), tb>>>(p_y, out);
}

// round 6
// speedup vs baseline: 3.5787x; 1.0479x over previous
#include <cuda_runtime.h>
#include <math.h>

#define B_    64
#define C_    384
#define N_    256
#define NT    (B_*N_)
#define INNER 256
#define HID   1536
#define HEADS 8
#define DHEAD 32

// ---------------- scratch ----------------
__device__ float g_t[NT*C_];
__device__ float g_a[NT*C_];
__device__ float g_f[NT*C_];
__device__ float g_qkv[NT*3*INNER];
__device__ float g_o[NT*INNER];
__device__ float g_attn[NT*C_];
__device__ float g_h[NT*HID];
__device__ float g_y[NT*C_];
// transposed weights [N][K]
__device__ float g_wqkvT[768*384];
__device__ float g_woutT[384*256];
__device__ float g_wff1T[1536*384];
__device__ float g_wff2T[384*1536];

// ---------------- asm helpers ----------------
__device__ __forceinline__ void cp_async16(void* dst, const void* src) {
    unsigned d = (unsigned)__cvta_generic_to_shared(dst);
    asm volatile("cp.async.cg.shared.global [%0], [%1], 16;" :: "r"(d), "l"(src));
}
__device__ __forceinline__ void cp_commit() { asm volatile("cp.async.commit_group;"); }
template<int Np> __device__ __forceinline__ void cp_wait() {
    asm volatile("cp.async.wait_group %0;" :: "n"(Np));
}
__device__ __forceinline__ void mma_tf32(float* c, unsigned a0, unsigned a1, unsigned a2, unsigned a3,
                                         unsigned b0, unsigned b1) {
    asm volatile(
        "mma.sync.aligned.m16n8k8.row.col.f32.tf32.tf32.f32 "
        "{%0,%1,%2,%3}, {%4,%5,%6,%7}, {%8,%9}, {%0,%1,%2,%3};"
        : "+f"(c[0]), "+f"(c[1]), "+f"(c[2]), "+f"(c[3])
        : "r"(a0), "r"(a1), "r"(a2), "r"(a3), "r"(b0), "r"(b1));
}
__device__ __forceinline__ void ldsm4(unsigned &r0, unsigned &r1, unsigned &r2, unsigned &r3,
                                      const float* p) {
    unsigned a = (unsigned)__cvta_generic_to_shared(p);
    asm volatile("ldmatrix.sync.aligned.m8n8.x4.shared.b16 {%0,%1,%2,%3}, [%4];"
        : "=r"(r0), "=r"(r1), "=r"(r2), "=r"(r3) : "r"(a));
}

// ---------------- transpose: in [B, R, Cc] -> out [B, Cc, R] ----------------
template<int R, int Cc>
__global__ void transpose_kernel(const float* __restrict__ in, float* __restrict__ out) {
    __shared__ float tile[32][33];
    int b  = blockIdx.z;
    int c0 = blockIdx.x * 32;
    int r0 = blockIdx.y * 32;
    const float* inb  = in  + (size_t)b * R * Cc;
    float*       outb = out + (size_t)b * R * Cc;
    #pragma unroll
    for (int i = threadIdx.y; i < 32; i += 8)
        tile[i][threadIdx.x] = inb[(size_t)(r0 + i) * Cc + c0 + threadIdx.x];
    __syncthreads();
    #pragma unroll
    for (int i = threadIdx.y; i < 32; i += 8)
        outb[(size_t)(c0 + i) * R + r0 + threadIdx.x] = tile[threadIdx.x][i];
}

// ---------------- dual layernorm ----------------
__global__ void __launch_bounds__(128) ln_dual_kernel(
    const float* __restrict__ g1, const float* __restrict__ b1,
    const float* __restrict__ g2, const float* __restrict__ b2) {
    int token = blockIdx.x;
    const float* tp = g_t + (size_t)token * C_;
    int tid = threadIdx.x;
    float v[3];
    float s = 0.f, ss = 0.f;
    #pragma unroll
    for (int i = 0; i < 3; i++) {
        v[i] = tp[tid + i * 128];
        s += v[i]; ss += v[i] * v[i];
    }
    #pragma unroll
    for (int o = 16; o > 0; o >>= 1) {
        s  += __shfl_down_sync(0xffffffffu, s,  o);
        ss += __shfl_down_sync(0xffffffffu, ss, o);
    }
    __shared__ float rs[4], rss[4];
    __shared__ float s_mean, s_rstd;
    if ((tid & 31) == 0) { rs[tid >> 5] = s; rss[tid >> 5] = ss; }
    __syncthreads();
    if (tid == 0) {
        float S  = rs[0] + rs[1] + rs[2] + rs[3];
        float SS = rss[0] + rss[1] + rss[2] + rss[3];
        float mean = S / (float)C_;
        float var  = SS / (float)C_ - mean * mean;
        s_mean = mean;
        s_rstd = rsqrtf(var + 1e-5f);
    }
    __syncthreads();
    float mean = s_mean, rstd = s_rstd;
    #pragma unroll
    for (int i = 0; i < 3; i++) {
        int c = tid + i * 128;
        float xn = (v[i] - mean) * rstd;
        g_a[(size_t)token * C_ + c] = xn * g1[c] + b1[c];
        g_f[(size_t)token * C_ + c] = xn * g2[c] + b2[c];
    }
}

// ---------------- tf32 GEMM: C[M,N] = A[M,K] @ B[K,N], B given TRANSPOSED [N][K] ----------------
// EPI: 0 none, 1 +bias, 2 gelu(+bias), 3 +bias + r1 + r2
#define SA 36
#define STAGE_W (128*SA*2)      // A tile + B tile, both 128x32 stride 36

template<int EPI>
__global__ void __launch_bounds__(128, 2) mma_gemm(
    const float* __restrict__ A, const float* __restrict__ BT, float* __restrict__ Cm,
    int M, int N, int K,
    const float* __restrict__ bias,
    const float* __restrict__ r1, const float* __restrict__ r2) {
    extern __shared__ float sh[];

    int bm = blockIdx.y * 128, bn = blockIdx.x * 128;
    int tid  = threadIdx.x;
    int wid  = tid >> 5, lane = tid & 31;
    int g    = lane >> 2, tig = lane & 3;
    int m_off = (wid & 1) * 64;
    int n_off = (wid >> 1) * 64;

    // ldmatrix per-lane offsets (words)
    int aoff = (lane & 15) * SA + (lane >> 4) * 4;
    int boff = (((lane >> 4) << 3) + (lane & 7)) * SA + ((lane >> 3) & 1) * 4;

    float acc[4][8][4];
    #pragma unroll
    for (int mt = 0; mt < 4; mt++)
        #pragma unroll
        for (int nt = 0; nt < 8; nt++)
            #pragma unroll
            for (int c = 0; c < 4; c++) acc[mt][nt][c] = 0.f;

    int lr  = tid >> 3;          // row base (0..15), +16*l
    int lc4 = (tid & 7) * 4;     // k offset

    int nIter = K >> 5;

    // prologue
    {
        float* Ab = sh;
        float* Bb = sh + 128 * SA;
        #pragma unroll
        for (int l = 0; l < 8; l++) {
            int r = lr + l * 16;
            cp_async16(&Ab[r * SA + lc4], A  + (size_t)(bm + r) * K + lc4);
            cp_async16(&Bb[r * SA + lc4], BT + (size_t)(bn + r) * K + lc4);
        }
        cp_commit();
    }

    for (int it = 0; it < nIter; it++) {
        if (it + 1 < nIter) {
            int k0 = (it + 1) * 32;
            float* Ab = sh + ((it + 1) & 1) * STAGE_W;
            float* Bb = Ab + 128 * SA;
            #pragma unroll
            for (int l = 0; l < 8; l++) {
                int r = lr + l * 16;
                cp_async16(&Ab[r * SA + lc4], A  + (size_t)(bm + r) * K + k0 + lc4);
                cp_async16(&Bb[r * SA + lc4], BT + (size_t)(bn + r) * K + k0 + lc4);
            }
            cp_commit();
            cp_wait<1>();
        } else {
            cp_wait<0>();
        }
        __syncthreads();

        const float* As = sh + (it & 1) * STAGE_W;
        const float* Bs = As + 128 * SA;

        #pragma unroll
        for (int kk = 0; kk < 4; kk++) {
            unsigned bfr[8][2];
            #pragma unroll
            for (int nt2 = 0; nt2 < 4; nt2++)
                ldsm4(bfr[2*nt2][0], bfr[2*nt2][1], bfr[2*nt2+1][0], bfr[2*nt2+1][1],
                      Bs + (n_off + nt2 * 16) * SA + kk * 8 + boff);
            #pragma unroll
            for (int mt = 0; mt < 4; mt++) {
                unsigned a0, a1, a2, a3;
                ldsm4(a0, a1, a2, a3, As + (m_off + mt * 16) * SA + kk * 8 + aoff);
                #pragma unroll
                for (int nt = 0; nt < 8; nt++)
                    mma_tf32(acc[mt][nt], a0, a1, a2, a3, bfr[nt][0], bfr[nt][1]);
            }
        }
        __syncthreads();
    }

    // epilogue
    #pragma unroll
    for (int mt = 0; mt < 4; mt++) {
        int row0 = bm + m_off + mt * 16 + g;
        #pragma unroll
        for (int nt = 0; nt < 8; nt++) {
            int col = bn + n_off + nt * 8 + 2 * tig;
            #pragma unroll
            for (int half = 0; half < 2; half++) {
                int row = row0 + half * 8;
                float v0 = acc[mt][nt][half * 2 + 0];
                float v1 = acc[mt][nt][half * 2 + 1];
                if (EPI >= 1) { v0 += bias[col]; v1 += bias[col + 1]; }
                if (EPI == 2) {
                    v0 = 0.5f * v0 * (1.0f + erff(v0 * 0.70710678118654752f));
                    v1 = 0.5f * v1 * (1.0f + erff(v1 * 0.70710678118654752f));
                }
                size_t idx = (size_t)row * N + col;
                if (EPI == 3) {
                    v0 += r1[idx] + r2[idx];
                    v1 += r1[idx + 1] + r2[idx + 1];
                }
                *(float2*)(Cm + idx) = make_float2(v0, v1);
            }
        }
    }
}

// ---------------- tensor-core attention ----------------
#define PS 68
#define ATT_SMEM_W (256*36 + 256*36 + 8*32*PS + 961)
__global__ void __launch_bounds__(256) attn_tc_kernel(const float* __restrict__ bias_table) {
    extern __shared__ float sm[];
    float* ks = sm;
    float* vs = ks + 256 * 36;
    float* qp = vs + 256 * 36;      // Q staging (stride 36), later per-warp P (stride 68)
    float* bt = qp + 8 * 32 * PS;
    int b = blockIdx.x >> 3;
    int h = blockIdx.x & 7;
    int tid = threadIdx.x, w = tid >> 5, lane = tid & 31;
    int g = lane >> 2, tig = lane & 3;
    const float* qkvb = g_qkv + (size_t)b * N_ * 768;

    int aoffp = (lane & 15) * PS + (lane >> 4) * 4;
    int boffk = (((lane >> 4) << 3) + (lane & 7)) * 36 + ((lane >> 3) & 1) * 4;

    #pragma unroll
    for (int it = 0; it < 8; it++) {
        int idx = tid + it * 256;
        int j = idx >> 3, d4 = (idx & 7) * 4;
        const float* base = qkvb + (size_t)j * 768 + h * 32 + d4;
        float4 qv = *(const float4*)(base);
        qv.x *= 0.17677669529663689f; qv.y *= 0.17677669529663689f;
        qv.z *= 0.17677669529663689f; qv.w *= 0.17677669529663689f;
        *(float4*)(qp + j * 36 + d4) = qv;
        *(float4*)(ks + j * 36 + d4) = *(const float4*)(base + 256);
        *(float4*)(vs + j * 36 + d4) = *(const float4*)(base + 512);
    }
    for (int t = tid; t < 961; t += 256)
        bt[t] = bias_table[t * HEADS + h];
    __syncthreads();

    int qb = w * 32;
    unsigned qa[2][4][4];
    #pragma unroll
    for (int mt = 0; mt < 2; mt++)
        #pragma unroll
        for (int kk = 0; kk < 4; kk++) {
            int r0 = (qb + mt * 16 + g) * 36;
            int r1 = r0 + 8 * 36;
            qa[mt][kk][0] = __float_as_uint(qp[r0 + kk * 8 + tig]);
            qa[mt][kk][1] = __float_as_uint(qp[r1 + kk * 8 + tig]);
            qa[mt][kk][2] = __float_as_uint(qp[r0 + kk * 8 + tig + 4]);
            qa[mt][kk][3] = __float_as_uint(qp[r1 + kk * 8 + tig + 4]);
        }
    __syncthreads();

    float* ps = qp + w * 32 * PS;

    float mrow[2][2], lrow[2][2];
    #pragma unroll
    for (int mt = 0; mt < 2; mt++) { mrow[mt][0] = mrow[mt][1] = -1e30f; lrow[mt][0] = lrow[mt][1] = 0.f; }
    float acc[2][4][4];
    #pragma unroll
    for (int mt = 0; mt < 2; mt++)
        #pragma unroll
        for (int nt = 0; nt < 4; nt++)
            #pragma unroll
            for (int c = 0; c < 4; c++) acc[mt][nt][c] = 0.f;

    int yi[2][2], xi[2][2];
    #pragma unroll
    for (int mt = 0; mt < 2; mt++)
        #pragma unroll
        for (int hf = 0; hf < 2; hf++) {
            int i = qb + mt * 16 + g + 8 * hf;
            yi[mt][hf] = i >> 4; xi[mt][hf] = i & 15;
        }

    for (int jt = 0; jt < 4; jt++) {
        int jb = jt * 64;
        float s[2][8][4];
        #pragma unroll
        for (int mt = 0; mt < 2; mt++)
            #pragma unroll
            for (int nj = 0; nj < 8; nj++)
                #pragma unroll
                for (int c = 0; c < 4; c++) s[mt][nj][c] = 0.f;

        // S = Q K^T  (K fragments via ldmatrix)
        #pragma unroll
        for (int kk = 0; kk < 4; kk++) {
            unsigned bf[8][2];
            #pragma unroll
            for (int nj2 = 0; nj2 < 4; nj2++)
                ldsm4(bf[2*nj2][0], bf[2*nj2][1], bf[2*nj2+1][0], bf[2*nj2+1][1],
                      ks + (jb + nj2 * 16) * 36 + kk * 8 + boffk);
            #pragma unroll
            for (int mt = 0; mt < 2; mt++)
                #pragma unroll
                for (int nj = 0; nj < 8; nj++)
                    mma_tf32(s[mt][nj], qa[mt][kk][0], qa[mt][kk][1], qa[mt][kk][2], qa[mt][kk][3],
                             bf[nj][0], bf[nj][1]);
        }

        // bias add
        #pragma unroll
        for (int mt = 0; mt < 2; mt++)
            #pragma unroll
            for (int nj = 0; nj < 8; nj++)
                #pragma unroll
                for (int c = 0; c < 4; c++) {
                    int hf = c >> 1;
                    int j = jb + nj * 8 + 2 * tig + (c & 1);
                    int bidx = (yi[mt][hf] - (j >> 4) + 15) * 31 + (xi[mt][hf] - (j & 15) + 15);
                    s[mt][nj][c] += bt[bidx];
                }

        // online softmax
        #pragma unroll
        for (int mt = 0; mt < 2; mt++)
            #pragma unroll
            for (int hf = 0; hf < 2; hf++) {
                float tm = -1e30f;
                #pragma unroll
                for (int nj = 0; nj < 8; nj++)
                    tm = fmaxf(tm, fmaxf(s[mt][nj][hf*2], s[mt][nj][hf*2+1]));
                tm = fmaxf(tm, __shfl_xor_sync(0xffffffffu, tm, 1));
                tm = fmaxf(tm, __shfl_xor_sync(0xffffffffu, tm, 2));
                float nm = fmaxf(mrow[mt][hf], tm);
                float scale = __expf(mrow[mt][hf] - nm);
                mrow[mt][hf] = nm;
                float rs = 0.f;
                #pragma unroll
                for (int nj = 0; nj < 8; nj++) {
                    float p0 = __expf(s[mt][nj][hf*2]   - nm);
                    float p1 = __expf(s[mt][nj][hf*2+1] - nm);
                    s[mt][nj][hf*2] = p0; s[mt][nj][hf*2+1] = p1;
                    rs += p0 + p1;
                }
                rs += __shfl_xor_sync(0xffffffffu, rs, 1);
                rs += __shfl_xor_sync(0xffffffffu, rs, 2);
                lrow[mt][hf] = lrow[mt][hf] * scale + rs;
                #pragma unroll
                for (int nt = 0; nt < 4; nt++) {
                    acc[mt][nt][hf*2]   *= scale;
                    acc[mt][nt][hf*2+1] *= scale;
                }
            }

        // write P
        #pragma unroll
        for (int mt = 0; mt < 2; mt++)
            #pragma unroll
            for (int nj = 0; nj < 8; nj++) {
                int r0 = (mt * 16 + g) * PS + nj * 8 + 2 * tig;
                *(float2*)(ps + r0)          = make_float2(s[mt][nj][0], s[mt][nj][1]);
                *(float2*)(ps + r0 + 8 * PS) = make_float2(s[mt][nj][2], s[mt][nj][3]);
            }
        __syncwarp();

        // O += P V  (P fragments via ldmatrix; V fragments scalar)
        #pragma unroll
        for (int kk2 = 0; kk2 < 8; kk2++) {
            unsigned pa[2][4];
            #pragma unroll
            for (int mt = 0; mt < 2; mt++)
                ldsm4(pa[mt][0], pa[mt][1], pa[mt][2], pa[mt][3],
                      ps + (mt * 16) * PS + kk2 * 8 + aoffp);
            unsigned vb[4][2];
            #pragma unroll
            for (int nt = 0; nt < 4; nt++) {
                vb[nt][0] = __float_as_uint(vs[(jb + kk2 * 8 + tig)     * 36 + nt * 8 + g]);
                vb[nt][1] = __float_as_uint(vs[(jb + kk2 * 8 + tig + 4) * 36 + nt * 8 + g]);
            }
            #pragma unroll
            for (int mt = 0; mt < 2; mt++)
                #pragma unroll
                for (int nt = 0; nt < 4; nt++)
                    mma_tf32(acc[mt][nt], pa[mt][0], pa[mt][1], pa[mt][2], pa[mt][3],
                             vb[nt][0], vb[nt][1]);
        }
        __syncwarp();
    }

    // normalize + store
    #pragma unroll
    for (int mt = 0; mt < 2; mt++) {
        float inv0 = 1.0f / lrow[mt][0];
        float inv1 = 1.0f / lrow[mt][1];
        int tok0 = b * N_ + qb + mt * 16 + g;
        int tok1 = tok0 + 8;
        #pragma unroll
        for (int nt = 0; nt < 4; nt++) {
            int col = h * 32 + nt * 8 + 2 * tig;
            *(float2*)(g_o + (size_t)tok0 * INNER + col) =
                make_float2(acc[mt][nt][0] * inv0, acc[mt][nt][1] * inv0);
            *(float2*)(g_o + (size_t)tok1 * INNER + col) =
                make_float2(acc[mt][nt][2] * inv1, acc[mt][nt][3] * inv1);
        }
    }
}

// ---------------- launch ----------------
extern "C" void kernel_launch(void* const* d_in, const int* in_sizes, int n_in,
                              void* d_out, int out_size) {
    const float* x      = (const float*)d_in[0];
    const float* ln1_g  = (const float*)d_in[1];
    const float* ln1_b  = (const float*)d_in[2];
    const float* w_qkv  = (const float*)d_in[3];
    const float* btab   = (const float*)d_in[4];
    const float* w_out  = (const float*)d_in[5];
    const float* b_out  = (const float*)d_in[6];
    const float* ln2_g  = (const float*)d_in[7];
    const float* ln2_b  = (const float*)d_in[8];
    const float* w_ff1  = (const float*)d_in[9];
    const float* b_ff1  = (const float*)d_in[10];
    const float* w_ff2  = (const float*)d_in[11];
    const float* b_ff2  = (const float*)d_in[12];
    float* out = (float*)d_out;

    float *p_t, *p_a, *p_f, *p_qkv, *p_o, *p_attn, *p_h, *p_y;
    float *p_wqkvT, *p_woutT, *p_wff1T, *p_wff2T;
    cudaGetSymbolAddress((void**)&p_t,     g_t);
    cudaGetSymbolAddress((void**)&p_a,     g_a);
    cudaGetSymbolAddress((void**)&p_f,     g_f);
    cudaGetSymbolAddress((void**)&p_qkv,   g_qkv);
    cudaGetSymbolAddress((void**)&p_o,     g_o);
    cudaGetSymbolAddress((void**)&p_attn,  g_attn);
    cudaGetSymbolAddress((void**)&p_h,     g_h);
    cudaGetSymbolAddress((void**)&p_y,     g_y);
    cudaGetSymbolAddress((void**)&p_wqkvT, g_wqkvT);
    cudaGetSymbolAddress((void**)&p_woutT, g_woutT);
    cudaGetSymbolAddress((void**)&p_wff1T, g_wff1T);
    cudaGetSymbolAddress((void**)&p_wff2T, g_wff2T);

    int gemm_smem = STAGE_W * 2 * (int)sizeof(float);
    cudaFuncSetAttribute(mma_gemm<0>, cudaFuncAttributeMaxDynamicSharedMemorySize, gemm_smem);
    cudaFuncSetAttribute(mma_gemm<1>, cudaFuncAttributeMaxDynamicSharedMemorySize, gemm_smem);
    cudaFuncSetAttribute(mma_gemm<2>, cudaFuncAttributeMaxDynamicSharedMemorySize, gemm_smem);
    cudaFuncSetAttribute(mma_gemm<3>, cudaFuncAttributeMaxDynamicSharedMemorySize, gemm_smem);
    int attn_smem = ATT_SMEM_W * (int)sizeof(float);
    cudaFuncSetAttribute(attn_tc_kernel, cudaFuncAttributeMaxDynamicSharedMemorySize, attn_smem);

    dim3 tb(32, 8);

    // weight transposes [K,N] -> [N,K]
    transpose_kernel<C_,   3*INNER><<<dim3((3*INNER)/32, C_/32, 1), tb>>>(w_qkv, p_wqkvT);
    transpose_kernel<INNER, C_    ><<<dim3(C_/32, INNER/32, 1), tb>>>(w_out, p_woutT);
    transpose_kernel<C_,    HID   ><<<dim3(HID/32, C_/32, 1), tb>>>(w_ff1, p_wff1T);
    transpose_kernel<HID,   C_    ><<<dim3(C_/32, HID/32, 1), tb>>>(w_ff2, p_wff2T);

    // 1. x [B, C, n] -> t [B, n, C]
    transpose_kernel<C_, N_><<<dim3(N_/32, C_/32, B_), tb>>>(x, p_t);

    // 2. dual layernorm
    ln_dual_kernel<<<NT, 128>>>(ln1_g, ln1_b, ln2_g, ln2_b);

    // 3. qkv = a @ w_qkv
    mma_gemm<0><<<dim3((3*INNER)/128, NT/128), 128, gemm_smem>>>(
        p_a, p_wqkvT, p_qkv, NT, 3*INNER, C_, nullptr, nullptr, nullptr);

    // 4. attention
    attn_tc_kernel<<<B_ * HEADS, 256, attn_smem>>>(btab);

    // 5. attn_out = o @ w_out + b_out
    mma_gemm<1><<<dim3(C_/128, NT/128), 128, gemm_smem>>>(
        p_o, p_woutT, p_attn, NT, C_, INNER, b_out, nullptr, nullptr);

    // 6. h = gelu(f @ w_ff1 + b_ff1)
    mma_gemm<2><<<dim3(HID/128, NT/128), 128, gemm_smem>>>(
        p_f, p_wff1T, p_h, NT, HID, C_, b_ff1, nullptr, nullptr);

    // 7. y = h @ w_ff2 + b_ff2 + t + attn_out
    mma_gemm<3><<<dim3(C_/128, NT/128), 128, gemm_smem>>>(
        p_h, p_wff2T, p_y, NT, C_, HID, b_ff2, p_t, p_attn);

    // 8. y [B, n, C] -> out [B, C, n]
    transpose_kernel<N_, C_><<<dim3(C_/32, N_/32, B_), tb>>>(p_y, out);
}

// round 10
// speedup vs baseline: 4.6663x; 1.3039x over previous
#include <cuda_runtime.h>
#include <cuda_fp16.h>
#include <math.h>
#include <stdint.h>

#define B_    64
#define C_    384
#define N_    256
#define NT    (B_*N_)
#define INNER 256
#define HID   1536
#define HEADS 8
#define DHEAD 32

// ---------------- scratch ----------------
__device__ float  g_t[NT*C_];
__device__ __half g_a16[NT*C_];
__device__ __half g_f16[NT*C_];
__device__ __half g_qkv16[NT*3*INNER];
__device__ __half g_o16[NT*INNER];
__device__ float  g_attn[NT*C_];
__device__ __half g_h16[NT*HID];
__device__ float  g_y[NT*C_];
// transposed fp16 weights [N][K]
__device__ __half g_wqkvT[768*384];
__device__ __half g_woutT[384*256];
__device__ __half g_wff1T[1536*384];
__device__ __half g_wff2T[384*1536];

// ---------------- helpers ----------------
__device__ __forceinline__ void cp_async16(void* dst, const void* src) {
    unsigned d = (unsigned)__cvta_generic_to_shared(dst);
    asm volatile("cp.async.cg.shared.global [%0], [%1], 16;" :: "r"(d), "l"(src));
}
__device__ __forceinline__ void cp_commit() { asm volatile("cp.async.commit_group;"); }
template<int Np> __device__ __forceinline__ void cp_wait() {
    asm volatile("cp.async.wait_group %0;" :: "n"(Np));
}
__device__ __forceinline__ void mma_f16(float* c, unsigned a0, unsigned a1, unsigned a2, unsigned a3,
                                        unsigned b0, unsigned b1) {
    asm volatile(
        "mma.sync.aligned.m16n8k16.row.col.f32.f16.f16.f32 "
        "{%0,%1,%2,%3}, {%4,%5,%6,%7}, {%8,%9}, {%0,%1,%2,%3};"
        : "+f"(c[0]), "+f"(c[1]), "+f"(c[2]), "+f"(c[3])
        : "r"(a0), "r"(a1), "r"(a2), "r"(a3), "r"(b0), "r"(b1));
}
__device__ __forceinline__ void mma_tf32(float* c, unsigned a0, unsigned a1, unsigned a2, unsigned a3,
                                         unsigned b0, unsigned b1) {
    asm volatile(
        "mma.sync.aligned.m16n8k8.row.col.f32.tf32.tf32.f32 "
        "{%0,%1,%2,%3}, {%4,%5,%6,%7}, {%8,%9}, {%0,%1,%2,%3};"
        : "+f"(c[0]), "+f"(c[1]), "+f"(c[2]), "+f"(c[3])
        : "r"(a0), "r"(a1), "r"(a2), "r"(a3), "r"(b0), "r"(b1));
}
__device__ __forceinline__ void ldsm4(unsigned &r0, unsigned &r1, unsigned &r2, unsigned &r3,
                                      const void* p) {
    unsigned a = (unsigned)__cvta_generic_to_shared(p);
    asm volatile("ldmatrix.sync.aligned.m8n8.x4.shared.b16 {%0,%1,%2,%3}, [%4];"
        : "=r"(r0), "=r"(r1), "=r"(r2), "=r"(r3) : "r"(a));
}

// ---------------- transpose (fp32 -> fp32) ----------------
template<int R, int Cc>
__global__ void transpose_kernel(const float* __restrict__ in, float* __restrict__ out) {
    __shared__ float tile[32][33];
    int b  = blockIdx.z;
    int c0 = blockIdx.x * 32;
    int r0 = blockIdx.y * 32;
    const float* inb  = in  + (size_t)b * R * Cc;
    float*       outb = out + (size_t)b * R * Cc;
    #pragma unroll
    for (int i = threadIdx.y; i < 32; i += 8)
        tile[i][threadIdx.x] = inb[(size_t)(r0 + i) * Cc + c0 + threadIdx.x];
    __syncthreads();
    #pragma unroll
    for (int i = threadIdx.y; i < 32; i += 8)
        outb[(size_t)(c0 + i) * R + r0 + threadIdx.x] = tile[threadIdx.x][i];
}

// ---------------- transpose (fp32 -> fp16) for weights ----------------
template<int R, int Cc>
__global__ void transpose_f16_kernel(const float* __restrict__ in, __half* __restrict__ out) {
    __shared__ float tile[32][33];
    int c0 = blockIdx.x * 32;
    int r0 = blockIdx.y * 32;
    #pragma unroll
    for (int i = threadIdx.y; i < 32; i += 8)
        tile[i][threadIdx.x] = in[(size_t)(r0 + i) * Cc + c0 + threadIdx.x];
    __syncthreads();
    #pragma unroll
    for (int i = threadIdx.y; i < 32; i += 8)
        out[(size_t)(c0 + i) * R + r0 + threadIdx.x] = __float2half(tile[threadIdx.x][i]);
}

// ---------------- dual layernorm: reads g_t, writes fp16 a/f ----------------
__global__ void __launch_bounds__(128) ln_dual_kernel(
    const float* __restrict__ g1, const float* __restrict__ b1,
    const float* __restrict__ g2, const float* __restrict__ b2) {
    int token = blockIdx.x;
    const float* tp = g_t + (size_t)token * C_;
    int tid = threadIdx.x;
    float v[3];
    float s = 0.f, ss = 0.f;
    #pragma unroll
    for (int i = 0; i < 3; i++) {
        v[i] = tp[tid + i * 128];
        s += v[i]; ss += v[i] * v[i];
    }
    #pragma unroll
    for (int o = 16; o > 0; o >>= 1) {
        s  += __shfl_down_sync(0xffffffffu, s,  o);
        ss += __shfl_down_sync(0xffffffffu, ss, o);
    }
    __shared__ float rs[4], rss[4];
    __shared__ float s_mean, s_rstd;
    if ((tid & 31) == 0) { rs[tid >> 5] = s; rss[tid >> 5] = ss; }
    __syncthreads();
    if (tid == 0) {
        float S  = rs[0] + rs[1] + rs[2] + rs[3];
        float SS = rss[0] + rss[1] + rss[2] + rss[3];
        float mean = S / (float)C_;
        float var  = SS / (float)C_ - mean * mean;
        s_mean = mean;
        s_rstd = rsqrtf(var + 1e-5f);
    }
    __syncthreads();
    float mean = s_mean, rstd = s_rstd;
    #pragma unroll
    for (int i = 0; i < 3; i++) {
        int c = tid + i * 128;
        float xn = (v[i] - mean) * rstd;
        g_a16[(size_t)token * C_ + c] = __float2half(xn * g1[c] + b1[c]);
        g_f16[(size_t)token * C_ + c] = __float2half(xn * g2[c] + b2[c]);
    }
}

// ---------------- fp16 tensor-core GEMM: C[M,N] = A[M,K] @ B, B TRANSPOSED [N][K] ----------------
// EPI: 0 none, 1 +bias, 2 gelu(+bias), 3 +bias+r1+r2.  OUTH: 1 -> write __half, 0 -> float
#define SH 40                       // halves per smem row (80B, conflict-free)
#define HSTG (128*SH*2)             // halves per stage (A tile + B tile)

template<int EPI, int OUTH>
__global__ void __launch_bounds__(128, 2) h_gemm(
    const __half* __restrict__ A, const __half* __restrict__ BT, void* __restrict__ Cout,
    int M, int N, int K,
    const float* __restrict__ bias,
    const float* __restrict__ r1, const float* __restrict__ r2) {
    extern __shared__ __half sh2[];

    int bm = blockIdx.y * 128, bn = blockIdx.x * 128;
    int tid  = threadIdx.x;
    int wid  = tid >> 5, lane = tid & 31;
    int g    = lane >> 2, tig = lane & 3;
    int m_off = (wid & 1) * 64;
    int n_off = (wid >> 1) * 64;

    // ldmatrix per-lane offsets (halves)
    int aoff = ((lane & 7) + ((lane >> 3) & 1) * 8) * SH + ((lane >> 4) & 1) * 8;
    int boff = ((lane & 7) + ((lane >> 4) & 1) * 8) * SH + ((lane >> 3) & 1) * 8;

    float acc[4][8][4];
    #pragma unroll
    for (int mt = 0; mt < 4; mt++)
        #pragma unroll
        for (int nt = 0; nt < 8; nt++)
            #pragma unroll
            for (int c = 0; c < 4; c++) acc[mt][nt][c] = 0.f;

    int nIter = K >> 5;

    // stage loader: per tile 128 rows x 32 halves = 512 x 16B chunks; 4/thread for A and B
    {
        __half* Ab = sh2;
        __half* Bb = sh2 + 128 * SH;
        #pragma unroll
        for (int l = 0; l < 4; l++) {
            int c = tid + l * 128;           // 0..511
            int r = c >> 2, h8 = (c & 3) * 8;
            cp_async16(Ab + r * SH + h8, A  + (size_t)(bm + r) * K + h8);
            cp_async16(Bb + r * SH + h8, BT + (size_t)(bn + r) * K + h8);
        }
        cp_commit();
    }

    for (int it = 0; it < nIter; it++) {
        if (it + 1 < nIter) {
            int k0 = (it + 1) * 32;
            __half* Ab = sh2 + ((it + 1) & 1) * HSTG;
            __half* Bb = Ab + 128 * SH;
            #pragma unroll
            for (int l = 0; l < 4; l++) {
                int c = tid + l * 128;
                int r = c >> 2, h8 = (c & 3) * 8;
                cp_async16(Ab + r * SH + h8, A  + (size_t)(bm + r) * K + k0 + h8);
                cp_async16(Bb + r * SH + h8, BT + (size_t)(bn + r) * K + k0 + h8);
            }
            cp_commit();
            cp_wait<1>();
        } else {
            cp_wait<0>();
        }
        __syncthreads();

        const __half* As = sh2 + (it & 1) * HSTG;
        const __half* Bs = As + 128 * SH;

        #pragma unroll
        for (int kk = 0; kk < 2; kk++) {      // two k16 steps per 32-k iter
            int kb = kk * 16;
            unsigned bfr[8][2];
            #pragma unroll
            for (int nt2 = 0; nt2 < 4; nt2++)
                ldsm4(bfr[2*nt2][0], bfr[2*nt2][1], bfr[2*nt2+1][0], bfr[2*nt2+1][1],
                      Bs + (n_off + nt2 * 16) * SH + kb + boff);
            #pragma unroll
            for (int mt = 0; mt < 4; mt++) {
                unsigned a0, a1, a2, a3;
                ldsm4(a0, a1, a2, a3, As + (m_off + mt * 16) * SH + kb + aoff);
                #pragma unroll
                for (int nt = 0; nt < 8; nt++)
                    mma_f16(acc[mt][nt], a0, a1, a2, a3, bfr[nt][0], bfr[nt][1]);
            }
        }
        __syncthreads();
    }

    // epilogue
    #pragma unroll
    for (int mt = 0; mt < 4; mt++) {
        int row0 = bm + m_off + mt * 16 + g;
        #pragma unroll
        for (int nt = 0; nt < 8; nt++) {
            int col = bn + n_off + nt * 8 + 2 * tig;
            #pragma unroll
            for (int half = 0; half < 2; half++) {
                int row = row0 + half * 8;
                float v0 = acc[mt][nt][half * 2 + 0];
                float v1 = acc[mt][nt][half * 2 + 1];
                if (EPI >= 1) { v0 += bias[col]; v1 += bias[col + 1]; }
                if (EPI == 2) {
                    v0 = 0.5f * v0 * (1.0f + erff(v0 * 0.70710678118654752f));
                    v1 = 0.5f * v1 * (1.0f + erff(v1 * 0.70710678118654752f));
                }
                size_t idx = (size_t)row * N + col;
                if (EPI == 3) {
                    v0 += r1[idx] + r2[idx];
                    v1 += r1[idx + 1] + r2[idx + 1];
                }
                if (OUTH)
                    *(__half2*)((__half*)Cout + idx) = __floats2half2_rn(v0, v1);
                else
                    *(float2*)((float*)Cout + idx) = make_float2(v0, v1);
            }
        }
    }
}

// ---------------- tensor-core attention (tf32, fp16 input/output) ----------------
#define PS 68
#define ATT_SMEM_W (256*36 + 256*36 + 8*32*PS + 961)
__global__ void __launch_bounds__(256) attn_tc_kernel(const float* __restrict__ bias_table) {
    extern __shared__ float sm[];
    float* ks = sm;
    float* vs = ks + 256 * 36;
    float* qp = vs + 256 * 36;
    float* bt = qp + 8 * 32 * PS;
    int b = blockIdx.x >> 3;
    int h = blockIdx.x & 7;
    int tid = threadIdx.x, w = tid >> 5, lane = tid & 31;
    int g = lane >> 2, tig = lane & 3;
    const __half* qkvb = g_qkv16 + (size_t)b * N_ * 768;

    int aoffp = (lane & 15) * PS + (lane >> 4) * 4;
    int boffk = (((lane >> 4) << 3) + (lane & 7)) * 36 + ((lane >> 3) & 1) * 4;

    #pragma unroll
    for (int it = 0; it < 8; it++) {
        int idx = tid + it * 256;
        int j = idx >> 3, d4 = (idx & 7) * 4;
        const __half* base = qkvb + (size_t)j * 768 + h * 32 + d4;
        float2 q01 = __half22float2(*(const __half2*)(base));
        float2 q23 = __half22float2(*(const __half2*)(base + 2));
        q01.x *= 0.17677669529663689f; q01.y *= 0.17677669529663689f;
        q23.x *= 0.17677669529663689f; q23.y *= 0.17677669529663689f;
        *(float2*)(qp + j * 36 + d4)     = q01;
        *(float2*)(qp + j * 36 + d4 + 2) = q23;
        *(float2*)(ks + j * 36 + d4)     = __half22float2(*(const __half2*)(base + 256));
        *(float2*)(ks + j * 36 + d4 + 2) = __half22float2(*(const __half2*)(base + 258));
        *(float2*)(vs + j * 36 + d4)     = __half22float2(*(const __half2*)(base + 512));
        *(float2*)(vs + j * 36 + d4 + 2) = __half22float2(*(const __half2*)(base + 514));
    }
    for (int t = tid; t < 961; t += 256)
        bt[t] = bias_table[t * HEADS + h];
    __syncthreads();

    int qb = w * 32;
    unsigned qa[2][4][4];
    #pragma unroll
    for (int mt = 0; mt < 2; mt++)
        #pragma unroll
        for (int kk = 0; kk < 4; kk++) {
            int r0 = (qb + mt * 16 + g) * 36;
            int r1 = r0 + 8 * 36;
            qa[mt][kk][0] = __float_as_uint(qp[r0 + kk * 8 + tig]);
            qa[mt][kk][1] = __float_as_uint(qp[r1 + kk * 8 + tig]);
            qa[mt][kk][2] = __float_as_uint(qp[r0 + kk * 8 + tig + 4]);
            qa[mt][kk][3] = __float_as_uint(qp[r1 + kk * 8 + tig + 4]);
        }
    __syncthreads();

    float* ps = qp + w * 32 * PS;

    float mrow[2][2], lrow[2][2];
    #pragma unroll
    for (int mt = 0; mt < 2; mt++) { mrow[mt][0] = mrow[mt][1] = -1e30f; lrow[mt][0] = lrow[mt][1] = 0.f; }
    float acc[2][4][4];
    #pragma unroll
    for (int mt = 0; mt < 2; mt++)
        #pragma unroll
        for (int nt = 0; nt < 4; nt++)
            #pragma unroll
            for (int c = 0; c < 4; c++) acc[mt][nt][c] = 0.f;

    int yi[2][2], xi[2][2];
    #pragma unroll
    for (int mt = 0; mt < 2; mt++)
        #pragma unroll
        for (int hf = 0; hf < 2; hf++) {
            int i = qb + mt * 16 + g + 8 * hf;
            yi[mt][hf] = i >> 4; xi[mt][hf] = i & 15;
        }

    for (int jt = 0; jt < 4; jt++) {
        int jb = jt * 64;
        float s[2][8][4];
        #pragma unroll
        for (int mt = 0; mt < 2; mt++)
            #pragma unroll
            for (int nj = 0; nj < 8; nj++)
                #pragma unroll
                for (int c = 0; c < 4; c++) s[mt][nj][c] = 0.f;

        #pragma unroll
        for (int kk = 0; kk < 4; kk++) {
            unsigned bf[8][2];
            #pragma unroll
            for (int nj2 = 0; nj2 < 4; nj2++)
                ldsm4(bf[2*nj2][0], bf[2*nj2][1], bf[2*nj2+1][0], bf[2*nj2+1][1],
                      ks + (jb + nj2 * 16) * 36 + kk * 8 + boffk);
            #pragma unroll
            for (int mt = 0; mt < 2; mt++)
                #pragma unroll
                for (int nj = 0; nj < 8; nj++)
                    mma_tf32(s[mt][nj], qa[mt][kk][0], qa[mt][kk][1], qa[mt][kk][2], qa[mt][kk][3],
                             bf[nj][0], bf[nj][1]);
        }

        #pragma unroll
        for (int mt = 0; mt < 2; mt++)
            #pragma unroll
            for (int nj = 0; nj < 8; nj++)
                #pragma unroll
                for (int c = 0; c < 4; c++) {
                    int hf = c >> 1;
                    int j = jb + nj * 8 + 2 * tig + (c & 1);
                    int bidx = (yi[mt][hf] - (j >> 4) + 15) * 31 + (xi[mt][hf] - (j & 15) + 15);
                    s[mt][nj][c] += bt[bidx];
                }

        #pragma unroll
        for (int mt = 0; mt < 2; mt++)
            #pragma unroll
            for (int hf = 0; hf < 2; hf++) {
                float tm = -1e30f;
                #pragma unroll
                for (int nj = 0; nj < 8; nj++)
                    tm = fmaxf(tm, fmaxf(s[mt][nj][hf*2], s[mt][nj][hf*2+1]));
                tm = fmaxf(tm, __shfl_xor_sync(0xffffffffu, tm, 1));
                tm = fmaxf(tm, __shfl_xor_sync(0xffffffffu, tm, 2));
                float nm = fmaxf(mrow[mt][hf], tm);
                float scale = __expf(mrow[mt][hf] - nm);
                mrow[mt][hf] = nm;
                float rs = 0.f;
                #pragma unroll
                for (int nj = 0; nj < 8; nj++) {
                    float p0 = __expf(s[mt][nj][hf*2]   - nm);
                    float p1 = __expf(s[mt][nj][hf*2+1] - nm);
                    s[mt][nj][hf*2] = p0; s[mt][nj][hf*2+1] = p1;
                    rs += p0 + p1;
                }
                rs += __shfl_xor_sync(0xffffffffu, rs, 1);
                rs += __shfl_xor_sync(0xffffffffu, rs, 2);
                lrow[mt][hf] = lrow[mt][hf] * scale + rs;
                #pragma unroll
                for (int nt = 0; nt < 4; nt++) {
                    acc[mt][nt][hf*2]   *= scale;
                    acc[mt][nt][hf*2+1] *= scale;
                }
            }

        #pragma unroll
        for (int mt = 0; mt < 2; mt++)
            #pragma unroll
            for (int nj = 0; nj < 8; nj++) {
                int r0 = (mt * 16 + g) * PS + nj * 8 + 2 * tig;
                *(float2*)(ps + r0)          = make_float2(s[mt][nj][0], s[mt][nj][1]);
                *(float2*)(ps + r0 + 8 * PS) = make_float2(s[mt][nj][2], s[mt][nj][3]);
            }
        __syncwarp();

        #pragma unroll
        for (int kk2 = 0; kk2 < 8; kk2++) {
            unsigned pa[2][4];
            #pragma unroll
            for (int mt = 0; mt < 2; mt++)
                ldsm4(pa[mt][0], pa[mt][1], pa[mt][2], pa[mt][3],
                      ps + (mt * 16) * PS + kk2 * 8 + aoffp);
            unsigned vb[4][2];
            #pragma unroll
            for (int nt = 0; nt < 4; nt++) {
                vb[nt][0] = __float_as_uint(vs[(jb + kk2 * 8 + tig)     * 36 + nt * 8 + g]);
                vb[nt][1] = __float_as_uint(vs[(jb + kk2 * 8 + tig + 4) * 36 + nt * 8 + g]);
            }
            #pragma unroll
            for (int mt = 0; mt < 2; mt++)
                #pragma unroll
                for (int nt = 0; nt < 4; nt++)
                    mma_tf32(acc[mt][nt], pa[mt][0], pa[mt][1], pa[mt][2], pa[mt][3],
                             vb[nt][0], vb[nt][1]);
        }
        __syncwarp();
    }

    #pragma unroll
    for (int mt = 0; mt < 2; mt++) {
        float inv0 = 1.0f / lrow[mt][0];
        float inv1 = 1.0f / lrow[mt][1];
        int tok0 = b * N_ + qb + mt * 16 + g;
        int tok1 = tok0 + 8;
        #pragma unroll
        for (int nt = 0; nt < 4; nt++) {
            int col = h * 32 + nt * 8 + 2 * tig;
            *(__half2*)(g_o16 + (size_t)tok0 * INNER + col) =
                __floats2half2_rn(acc[mt][nt][0] * inv0, acc[mt][nt][1] * inv0);
            *(__half2*)(g_o16 + (size_t)tok1 * INNER + col) =
                __floats2half2_rn(acc[mt][nt][2] * inv1, acc[mt][nt][3] * inv1);
        }
    }
}

// ---------------- launch ----------------
extern "C" void kernel_launch(void* const* d_in, const int* in_sizes, int n_in,
                              void* d_out, int out_size) {
    const float* x      = (const float*)d_in[0];
    const float* ln1_g  = (const float*)d_in[1];
    const float* ln1_b  = (const float*)d_in[2];
    const float* w_qkv  = (const float*)d_in[3];
    const float* btab   = (const float*)d_in[4];
    const float* w_out  = (const float*)d_in[5];
    const float* b_out  = (const float*)d_in[6];
    const float* ln2_g  = (const float*)d_in[7];
    const float* ln2_b  = (const float*)d_in[8];
    const float* w_ff1  = (const float*)d_in[9];
    const float* b_ff1  = (const float*)d_in[10];
    const float* w_ff2  = (const float*)d_in[11];
    const float* b_ff2  = (const float*)d_in[12];
    float* out = (float*)d_out;

    float  *p_t, *p_attn, *p_y;
    __half *p_a16, *p_f16, *p_qkv16, *p_o16, *p_h16;
    __half *p_wqkvT, *p_woutT, *p_wff1T, *p_wff2T;
    cudaGetSymbolAddress((void**)&p_t,     g_t);
    cudaGetSymbolAddress((void**)&p_a16,   g_a16);
    cudaGetSymbolAddress((void**)&p_f16,   g_f16);
    cudaGetSymbolAddress((void**)&p_qkv16, g_qkv16);
    cudaGetSymbolAddress((void**)&p_o16,   g_o16);
    cudaGetSymbolAddress((void**)&p_attn,  g_attn);
    cudaGetSymbolAddress((void**)&p_h16,   g_h16);
    cudaGetSymbolAddress((void**)&p_y,     g_y);
    cudaGetSymbolAddress((void**)&p_wqkvT, g_wqkvT);
    cudaGetSymbolAddress((void**)&p_woutT, g_woutT);
    cudaGetSymbolAddress((void**)&p_wff1T, g_wff1T);
    cudaGetSymbolAddress((void**)&p_wff2T, g_wff2T);

    int gemm_smem = HSTG * 2 * (int)sizeof(__half);   // 40960 B
    cudaFuncSetAttribute(h_gemm<0,1>, cudaFuncAttributeMaxDynamicSharedMemorySize, gemm_smem);
    cudaFuncSetAttribute(h_gemm<1,0>, cudaFuncAttributeMaxDynamicSharedMemorySize, gemm_smem);
    cudaFuncSetAttribute(h_gemm<2,1>, cudaFuncAttributeMaxDynamicSharedMemorySize, gemm_smem);
    cudaFuncSetAttribute(h_gemm<3,0>, cudaFuncAttributeMaxDynamicSharedMemorySize, gemm_smem);
    int attn_smem = ATT_SMEM_W * (int)sizeof(float);
    cudaFuncSetAttribute(attn_tc_kernel, cudaFuncAttributeMaxDynamicSharedMemorySize, attn_smem);

    dim3 tb(32, 8);

    // weight transposes [K,N] -> fp16 [N,K]
    transpose_f16_kernel<C_,   3*INNER><<<dim3((3*INNER)/32, C_/32), tb>>>(w_qkv, p_wqkvT);
    transpose_f16_kernel<INNER, C_    ><<<dim3(C_/32, INNER/32), tb>>>(w_out, p_woutT);
    transpose_f16_kernel<C_,    HID   ><<<dim3(HID/32, C_/32), tb>>>(w_ff1, p_wff1T);
    transpose_f16_kernel<HID,   C_    ><<<dim3(C_/32, HID/32), tb>>>(w_ff2, p_wff2T);

    // 1. x [B, C, n] -> t [B, n, C]
    transpose_kernel<C_, N_><<<dim3(N_/32, C_/32, B_), tb>>>(x, p_t);

    // 2. dual layernorm -> fp16 a/f
    ln_dual_kernel<<<NT, 128>>>(ln1_g, ln1_b, ln2_g, ln2_b);

    // 3. qkv = a @ w_qkv  (fp16 out)
    h_gemm<0,1><<<dim3((3*INNER)/128, NT/128), 128, gemm_smem>>>(
        p_a16, p_wqkvT, p_qkv16, NT, 3*INNER, C_, nullptr, nullptr, nullptr);

    // 4. attention (fp16 in/out)
    attn_tc_kernel<<<B_ * HEADS, 256, attn_smem>>>(btab);

    // 5. attn_out = o @ w_out + b_out  (fp32 out)
    h_gemm<1,0><<<dim3(C_/128, NT/128), 128, gemm_smem>>>(
        p_o16, p_woutT, p_attn, NT, C_, INNER, b_out, nullptr, nullptr);

    // 6. h = gelu(f @ w_ff1 + b_ff1)  (fp16 out)
    h_gemm<2,1><<<dim3(HID/128, NT/128), 128, gemm_smem>>>(
        p_f16, p_wff1T, p_h16, NT, HID, C_, b_ff1, nullptr, nullptr);

    // 7. y = h @ w_ff2 + b_ff2 + t + attn_out  (fp32 out)
    h_gemm<3,0><<<dim3(C_/128, NT/128), 128, gemm_smem>>>(
        p_h16, p_wff2T, p_y, NT, C_, HID, b_ff2, p_t, p_attn);

    // 8. y [B, n, C] -> out [B, C, n]
    transpose_kernel<N_, C_><<<dim3(C_/32, N_/32, B_), tb>>>(p_y, out);
}

// round 11
// speedup vs baseline: 4.8850x; 1.0469x over previous
#include <cuda_runtime.h>
#include <cuda_fp16.h>
#include <math.h>
#include <stdint.h>

#define B_    64
#define C_    384
#define N_    256
#define NT    (B_*N_)
#define INNER 256
#define HID   1536
#define HEADS 8
#define DHEAD 32

// ---------------- scratch ----------------
__device__ float  g_t[NT*C_];
__device__ __half g_a16[NT*C_];
__device__ __half g_f16[NT*C_];
__device__ __half g_qkv16[NT*3*INNER];
__device__ __half g_o16[NT*INNER];
__device__ float  g_attn[NT*C_];
__device__ __half g_h16[NT*HID];
__device__ float  g_y[NT*C_];
// transposed fp16 weights [N][K]
__device__ __half g_wqkvT[768*384];
__device__ __half g_woutT[384*256];
__device__ __half g_wff1T[1536*384];
__device__ __half g_wff2T[384*1536];

// ---------------- helpers ----------------
__device__ __forceinline__ void cp_async16(void* dst, const void* src) {
    unsigned d = (unsigned)__cvta_generic_to_shared(dst);
    asm volatile("cp.async.cg.shared.global [%0], [%1], 16;" :: "r"(d), "l"(src));
}
__device__ __forceinline__ void cp_commit() { asm volatile("cp.async.commit_group;"); }
template<int Np> __device__ __forceinline__ void cp_wait() {
    asm volatile("cp.async.wait_group %0;" :: "n"(Np));
}
__device__ __forceinline__ void mma_f16(float* c, unsigned a0, unsigned a1, unsigned a2, unsigned a3,
                                        unsigned b0, unsigned b1) {
    asm volatile(
        "mma.sync.aligned.m16n8k16.row.col.f32.f16.f16.f32 "
        "{%0,%1,%2,%3}, {%4,%5,%6,%7}, {%8,%9}, {%0,%1,%2,%3};"
        : "+f"(c[0]), "+f"(c[1]), "+f"(c[2]), "+f"(c[3])
        : "r"(a0), "r"(a1), "r"(a2), "r"(a3), "r"(b0), "r"(b1));
}
__device__ __forceinline__ void ldsm4(unsigned &r0, unsigned &r1, unsigned &r2, unsigned &r3,
                                      const void* p) {
    unsigned a = (unsigned)__cvta_generic_to_shared(p);
    asm volatile("ldmatrix.sync.aligned.m8n8.x4.shared.b16 {%0,%1,%2,%3}, [%4];"
        : "=r"(r0), "=r"(r1), "=r"(r2), "=r"(r3) : "r"(a));
}
__device__ __forceinline__ void ldsm4t(unsigned &r0, unsigned &r1, unsigned &r2, unsigned &r3,
                                       const void* p) {
    unsigned a = (unsigned)__cvta_generic_to_shared(p);
    asm volatile("ldmatrix.sync.aligned.m8n8.x4.trans.shared.b16 {%0,%1,%2,%3}, [%4];"
        : "=r"(r0), "=r"(r1), "=r"(r2), "=r"(r3) : "r"(a));
}
__device__ __forceinline__ unsigned packh2(float a, float b) {
    __half2 h = __floats2half2_rn(a, b);
    return *reinterpret_cast<unsigned*>(&h);
}

// ---------------- transpose (fp32 -> fp32) ----------------
template<int R, int Cc>
__global__ void transpose_kernel(const float* __restrict__ in, float* __restrict__ out) {
    __shared__ float tile[32][33];
    int b  = blockIdx.z;
    int c0 = blockIdx.x * 32;
    int r0 = blockIdx.y * 32;
    const float* inb  = in  + (size_t)b * R * Cc;
    float*       outb = out + (size_t)b * R * Cc;
    #pragma unroll
    for (int i = threadIdx.y; i < 32; i += 8)
        tile[i][threadIdx.x] = inb[(size_t)(r0 + i) * Cc + c0 + threadIdx.x];
    __syncthreads();
    #pragma unroll
    for (int i = threadIdx.y; i < 32; i += 8)
        outb[(size_t)(c0 + i) * R + r0 + threadIdx.x] = tile[threadIdx.x][i];
}

// ---------------- transpose (fp32 -> fp16) for weights ----------------
template<int R, int Cc>
__global__ void transpose_f16_kernel(const float* __restrict__ in, __half* __restrict__ out) {
    __shared__ float tile[32][33];
    int c0 = blockIdx.x * 32;
    int r0 = blockIdx.y * 32;
    #pragma unroll
    for (int i = threadIdx.y; i < 32; i += 8)
        tile[i][threadIdx.x] = in[(size_t)(r0 + i) * Cc + c0 + threadIdx.x];
    __syncthreads();
    #pragma unroll
    for (int i = threadIdx.y; i < 32; i += 8)
        out[(size_t)(c0 + i) * R + r0 + threadIdx.x] = __float2half(tile[threadIdx.x][i]);
}

// ---------------- dual layernorm ----------------
__global__ void __launch_bounds__(128) ln_dual_kernel(
    const float* __restrict__ g1, const float* __restrict__ b1,
    const float* __restrict__ g2, const float* __restrict__ b2) {
    int token = blockIdx.x;
    const float* tp = g_t + (size_t)token * C_;
    int tid = threadIdx.x;
    float v[3];
    float s = 0.f, ss = 0.f;
    #pragma unroll
    for (int i = 0; i < 3; i++) {
        v[i] = tp[tid + i * 128];
        s += v[i]; ss += v[i] * v[i];
    }
    #pragma unroll
    for (int o = 16; o > 0; o >>= 1) {
        s  += __shfl_down_sync(0xffffffffu, s,  o);
        ss += __shfl_down_sync(0xffffffffu, ss, o);
    }
    __shared__ float rs[4], rss[4];
    __shared__ float s_mean, s_rstd;
    if ((tid & 31) == 0) { rs[tid >> 5] = s; rss[tid >> 5] = ss; }
    __syncthreads();
    if (tid == 0) {
        float S  = rs[0] + rs[1] + rs[2] + rs[3];
        float SS = rss[0] + rss[1] + rss[2] + rss[3];
        float mean = S / (float)C_;
        float var  = SS / (float)C_ - mean * mean;
        s_mean = mean;
        s_rstd = rsqrtf(var + 1e-5f);
    }
    __syncthreads();
    float mean = s_mean, rstd = s_rstd;
    #pragma unroll
    for (int i = 0; i < 3; i++) {
        int c = tid + i * 128;
        float xn = (v[i] - mean) * rstd;
        g_a16[(size_t)token * C_ + c] = __float2half(xn * g1[c] + b1[c]);
        g_f16[(size_t)token * C_ + c] = __float2half(xn * g2[c] + b2[c]);
    }
}

// ---------------- fp16 tensor-core GEMM (unchanged from 375us baseline) ----------------
#define SH 40
#define HSTG (128*SH*2)

template<int EPI, int OUTH>
__global__ void __launch_bounds__(128, 2) h_gemm(
    const __half* __restrict__ A, const __half* __restrict__ BT, void* __restrict__ Cout,
    int M, int N, int K,
    const float* __restrict__ bias,
    const float* __restrict__ r1, const float* __restrict__ r2) {
    extern __shared__ __half sh2[];

    int bm = blockIdx.y * 128, bn = blockIdx.x * 128;
    int tid  = threadIdx.x;
    int wid  = tid >> 5, lane = tid & 31;
    int g    = lane >> 2, tig = lane & 3;
    int m_off = (wid & 1) * 64;
    int n_off = (wid >> 1) * 64;

    int aoff = ((lane & 7) + ((lane >> 3) & 1) * 8) * SH + ((lane >> 4) & 1) * 8;
    int boff = ((lane & 7) + ((lane >> 4) & 1) * 8) * SH + ((lane >> 3) & 1) * 8;

    float acc[4][8][4];
    #pragma unroll
    for (int mt = 0; mt < 4; mt++)
        #pragma unroll
        for (int nt = 0; nt < 8; nt++)
            #pragma unroll
            for (int c = 0; c < 4; c++) acc[mt][nt][c] = 0.f;

    int nIter = K >> 5;

    {
        __half* Ab = sh2;
        __half* Bb = sh2 + 128 * SH;
        #pragma unroll
        for (int l = 0; l < 4; l++) {
            int c = tid + l * 128;
            int r = c >> 2, h8 = (c & 3) * 8;
            cp_async16(Ab + r * SH + h8, A  + (size_t)(bm + r) * K + h8);
            cp_async16(Bb + r * SH + h8, BT + (size_t)(bn + r) * K + h8);
        }
        cp_commit();
    }

    for (int it = 0; it < nIter; it++) {
        if (it + 1 < nIter) {
            int k0 = (it + 1) * 32;
            __half* Ab = sh2 + ((it + 1) & 1) * HSTG;
            __half* Bb = Ab + 128 * SH;
            #pragma unroll
            for (int l = 0; l < 4; l++) {
                int c = tid + l * 128;
                int r = c >> 2, h8 = (c & 3) * 8;
                cp_async16(Ab + r * SH + h8, A  + (size_t)(bm + r) * K + k0 + h8);
                cp_async16(Bb + r * SH + h8, BT + (size_t)(bn + r) * K + k0 + h8);
            }
            cp_commit();
            cp_wait<1>();
        } else {
            cp_wait<0>();
        }
        __syncthreads();

        const __half* As = sh2 + (it & 1) * HSTG;
        const __half* Bs = As + 128 * SH;

        #pragma unroll
        for (int kk = 0; kk < 2; kk++) {
            int kb = kk * 16;
            unsigned bfr[8][2];
            #pragma unroll
            for (int nt2 = 0; nt2 < 4; nt2++)
                ldsm4(bfr[2*nt2][0], bfr[2*nt2][1], bfr[2*nt2+1][0], bfr[2*nt2+1][1],
                      Bs + (n_off + nt2 * 16) * SH + kb + boff);
            #pragma unroll
            for (int mt = 0; mt < 4; mt++) {
                unsigned a0, a1, a2, a3;
                ldsm4(a0, a1, a2, a3, As + (m_off + mt * 16) * SH + kb + aoff);
                #pragma unroll
                for (int nt = 0; nt < 8; nt++)
                    mma_f16(acc[mt][nt], a0, a1, a2, a3, bfr[nt][0], bfr[nt][1]);
            }
        }
        __syncthreads();
    }

    #pragma unroll
    for (int mt = 0; mt < 4; mt++) {
        int row0 = bm + m_off + mt * 16 + g;
        #pragma unroll
        for (int nt = 0; nt < 8; nt++) {
            int col = bn + n_off + nt * 8 + 2 * tig;
            #pragma unroll
            for (int half = 0; half < 2; half++) {
                int row = row0 + half * 8;
                float v0 = acc[mt][nt][half * 2 + 0];
                float v1 = acc[mt][nt][half * 2 + 1];
                if (EPI >= 1) { v0 += bias[col]; v1 += bias[col + 1]; }
                if (EPI == 2) {
                    v0 = 0.5f * v0 * (1.0f + erff(v0 * 0.70710678118654752f));
                    v1 = 0.5f * v1 * (1.0f + erff(v1 * 0.70710678118654752f));
                }
                size_t idx = (size_t)row * N + col;
                if (EPI == 3) {
                    v0 += r1[idx] + r2[idx];
                    v1 += r1[idx + 1] + r2[idx + 1];
                }
                if (OUTH)
                    *(__half2*)((__half*)Cout + idx) = __floats2half2_rn(v0, v1);
                else
                    *(float2*)((float*)Cout + idx) = make_float2(v0, v1);
            }
        }
    }
}

// ---------------- fp16 tensor-core attention, register-resident P ----------------
#define SHV 40
#define ATT_SMEM_B (3*256*SHV*2 + 961*4)
__global__ void __launch_bounds__(256) attn_f16_kernel(const float* __restrict__ bias_table) {
    extern __shared__ char smc[];
    __half* ks = (__half*)smc;
    __half* vs = ks + 256 * SHV;
    __half* qh = vs + 256 * SHV;
    float*  bt = (float*)(qh + 256 * SHV);
    int b = blockIdx.x >> 3;
    int h = blockIdx.x & 7;
    int tid = threadIdx.x, w = tid >> 5, lane = tid & 31;
    int g = lane >> 2, tig = lane & 3;
    const __half* qkvb = g_qkv16 + (size_t)b * N_ * 768;

    // stage Q/K/V: 16B copies, [j][d] rows stride SHV
    #pragma unroll
    for (int l = 0; l < 4; l++) {
        int i = tid + l * 256;            // 0..1023
        int j = i >> 2, c8 = (i & 3) * 8;
        const __half* base = qkvb + (size_t)j * 768 + h * 32 + c8;
        *(uint4*)(qh + j * SHV + c8) = *(const uint4*)(base);
        *(uint4*)(ks + j * SHV + c8) = *(const uint4*)(base + 256);
        *(uint4*)(vs + j * SHV + c8) = *(const uint4*)(base + 512);
    }
    for (int t = tid; t < 961; t += 256)
        bt[t] = bias_table[t * HEADS + h];
    __syncthreads();

    int aoff = ((lane & 7) + ((lane >> 3) & 1) * 8) * SHV + ((lane >> 4) & 1) * 8;
    int boff = ((lane & 7) + ((lane >> 4) & 1) * 8) * SHV + ((lane >> 3) & 1) * 8;
    // trans (V) per-lane address: matrix m covers (k8=(m&1), n8=(m>>1))
    int tm_   = lane >> 3;
    int toff  = ((tm_ & 1) * 8 + (lane & 7)) * SHV + (tm_ >> 1) * 8;

    // Q fragments
    int qb = w * 32;
    unsigned qa[2][2][4];
    #pragma unroll
    for (int mt = 0; mt < 2; mt++)
        #pragma unroll
        for (int kk = 0; kk < 2; kk++)
            ldsm4(qa[mt][kk][0], qa[mt][kk][1], qa[mt][kk][2], qa[mt][kk][3],
                  qh + (qb + mt * 16) * SHV + kk * 16 + aoff);

    float mrow[2][2], lrow[2][2];
    #pragma unroll
    for (int mt = 0; mt < 2; mt++) { mrow[mt][0] = mrow[mt][1] = -1e30f; lrow[mt][0] = lrow[mt][1] = 0.f; }
    float acc[2][4][4];
    #pragma unroll
    for (int mt = 0; mt < 2; mt++)
        #pragma unroll
        for (int nt = 0; nt < 4; nt++)
            #pragma unroll
            for (int c = 0; c < 4; c++) acc[mt][nt][c] = 0.f;

    int yi[2][2], xi[2][2];
    #pragma unroll
    for (int mt = 0; mt < 2; mt++)
        #pragma unroll
        for (int hf = 0; hf < 2; hf++) {
            int i = qb + mt * 16 + g + 8 * hf;
            yi[mt][hf] = i >> 4; xi[mt][hf] = i & 15;
        }

    const float SCALE = 0.17677669529663689f;

    for (int jt = 0; jt < 4; jt++) {
        int jb = jt * 64;
        float s[2][8][4];
        #pragma unroll
        for (int mt = 0; mt < 2; mt++)
            #pragma unroll
            for (int nj = 0; nj < 8; nj++)
                #pragma unroll
                for (int c = 0; c < 4; c++) s[mt][nj][c] = 0.f;

        // S = Q K^T  (fp16, k=32 -> 2 k16 steps)
        #pragma unroll
        for (int kk = 0; kk < 2; kk++) {
            unsigned bf[8][2];
            #pragma unroll
            for (int nj2 = 0; nj2 < 4; nj2++)
                ldsm4(bf[2*nj2][0], bf[2*nj2][1], bf[2*nj2+1][0], bf[2*nj2+1][1],
                      ks + (jb + nj2 * 16) * SHV + kk * 16 + boff);
            #pragma unroll
            for (int mt = 0; mt < 2; mt++)
                #pragma unroll
                for (int nj = 0; nj < 8; nj++)
                    mma_f16(s[mt][nj], qa[mt][kk][0], qa[mt][kk][1], qa[mt][kk][2], qa[mt][kk][3],
                            bf[nj][0], bf[nj][1]);
        }

        // scale + bias
        #pragma unroll
        for (int mt = 0; mt < 2; mt++)
            #pragma unroll
            for (int nj = 0; nj < 8; nj++)
                #pragma unroll
                for (int c = 0; c < 4; c++) {
                    int hf = c >> 1;
                    int j = jb + nj * 8 + 2 * tig + (c & 1);
                    int bidx = (yi[mt][hf] - (j >> 4) + 15) * 31 + (xi[mt][hf] - (j & 15) + 15);
                    s[mt][nj][c] = fmaf(s[mt][nj][c], SCALE, bt[bidx]);
                }

        // online softmax
        #pragma unroll
        for (int mt = 0; mt < 2; mt++)
            #pragma unroll
            for (int hf = 0; hf < 2; hf++) {
                float tm = -1e30f;
                #pragma unroll
                for (int nj = 0; nj < 8; nj++)
                    tm = fmaxf(tm, fmaxf(s[mt][nj][hf*2], s[mt][nj][hf*2+1]));
                tm = fmaxf(tm, __shfl_xor_sync(0xffffffffu, tm, 1));
                tm = fmaxf(tm, __shfl_xor_sync(0xffffffffu, tm, 2));
                float nm = fmaxf(mrow[mt][hf], tm);
                float scale = __expf(mrow[mt][hf] - nm);
                mrow[mt][hf] = nm;
                float rs = 0.f;
                #pragma unroll
                for (int nj = 0; nj < 8; nj++) {
                    float p0 = __expf(s[mt][nj][hf*2]   - nm);
                    float p1 = __expf(s[mt][nj][hf*2+1] - nm);
                    s[mt][nj][hf*2] = p0; s[mt][nj][hf*2+1] = p1;
                    rs += p0 + p1;
                }
                rs += __shfl_xor_sync(0xffffffffu, rs, 1);
                rs += __shfl_xor_sync(0xffffffffu, rs, 2);
                lrow[mt][hf] = lrow[mt][hf] * scale + rs;
                #pragma unroll
                for (int nt = 0; nt < 4; nt++) {
                    acc[mt][nt][hf*2]   *= scale;
                    acc[mt][nt][hf*2+1] *= scale;
                }
            }

        // V fragments via ldmatrix.trans (shared across mt)
        unsigned vb[4][4][2];   // [k16 step][n8 group (d)][2]
        #pragma unroll
        for (int njp = 0; njp < 4; njp++)
            #pragma unroll
            for (int dh = 0; dh < 2; dh++) {
                unsigned r0, r1, r2, r3;
                ldsm4t(r0, r1, r2, r3, vs + (jb + njp * 16) * SHV + dh * 16 + toff);
                vb[njp][dh*2][0]   = r0; vb[njp][dh*2][1]   = r1;
                vb[njp][dh*2+1][0] = r2; vb[njp][dh*2+1][1] = r3;
            }

        // P (registers) @ V
        #pragma unroll
        for (int njp = 0; njp < 4; njp++) {
            unsigned pa[2][4];
            #pragma unroll
            for (int mt = 0; mt < 2; mt++) {
                pa[mt][0] = packh2(s[mt][2*njp][0],   s[mt][2*njp][1]);
                pa[mt][1] = packh2(s[mt][2*njp][2],   s[mt][2*njp][3]);
                pa[mt][2] = packh2(s[mt][2*njp+1][0], s[mt][2*njp+1][1]);
                pa[mt][3] = packh2(s[mt][2*njp+1][2], s[mt][2*njp+1][3]);
            }
            #pragma unroll
            for (int mt = 0; mt < 2; mt++)
                #pragma unroll
                for (int nt = 0; nt < 4; nt++)
                    mma_f16(acc[mt][nt], pa[mt][0], pa[mt][1], pa[mt][2], pa[mt][3],
                            vb[njp][nt][0], vb[njp][nt][1]);
        }
    }

    // normalize + store fp16
    #pragma unroll
    for (int mt = 0; mt < 2; mt++) {
        float inv0 = 1.0f / lrow[mt][0];
        float inv1 = 1.0f / lrow[mt][1];
        int tok0 = b * N_ + qb + mt * 16 + g;
        int tok1 = tok0 + 8;
        #pragma unroll
        for (int nt = 0; nt < 4; nt++) {
            int col = h * 32 + nt * 8 + 2 * tig;
            *(__half2*)(g_o16 + (size_t)tok0 * INNER + col) =
                __floats2half2_rn(acc[mt][nt][0] * inv0, acc[mt][nt][1] * inv0);
            *(__half2*)(g_o16 + (size_t)tok1 * INNER + col) =
                __floats2half2_rn(acc[mt][nt][2] * inv1, acc[mt][nt][3] * inv1);
        }
    }
}

// ---------------- launch ----------------
extern "C" void kernel_launch(void* const* d_in, const int* in_sizes, int n_in,
                              void* d_out, int out_size) {
    const float* x      = (const float*)d_in[0];
    const float* ln1_g  = (const float*)d_in[1];
    const float* ln1_b  = (const float*)d_in[2];
    const float* w_qkv  = (const float*)d_in[3];
    const float* btab   = (const float*)d_in[4];
    const float* w_out  = (const float*)d_in[5];
    const float* b_out  = (const float*)d_in[6];
    const float* ln2_g  = (const float*)d_in[7];
    const float* ln2_b  = (const float*)d_in[8];
    const float* w_ff1  = (const float*)d_in[9];
    const float* b_ff1  = (const float*)d_in[10];
    const float* w_ff2  = (const float*)d_in[11];
    const float* b_ff2  = (const float*)d_in[12];
    float* out = (float*)d_out;

    float  *p_t, *p_attn, *p_y;
    __half *p_a16, *p_f16, *p_qkv16, *p_o16, *p_h16;
    __half *p_wqkvT, *p_woutT, *p_wff1T, *p_wff2T;
    cudaGetSymbolAddress((void**)&p_t,     g_t);
    cudaGetSymbolAddress((void**)&p_a16,   g_a16);
    cudaGetSymbolAddress((void**)&p_f16,   g_f16);
    cudaGetSymbolAddress((void**)&p_qkv16, g_qkv16);
    cudaGetSymbolAddress((void**)&p_o16,   g_o16);
    cudaGetSymbolAddress((void**)&p_attn,  g_attn);
    cudaGetSymbolAddress((void**)&p_h16,   g_h16);
    cudaGetSymbolAddress((void**)&p_y,     g_y);
    cudaGetSymbolAddress((void**)&p_wqkvT, g_wqkvT);
    cudaGetSymbolAddress((void**)&p_woutT, g_woutT);
    cudaGetSymbolAddress((void**)&p_wff1T, g_wff1T);
    cudaGetSymbolAddress((void**)&p_wff2T, g_wff2T);

    int gemm_smem = HSTG * 2 * (int)sizeof(__half);
    cudaFuncSetAttribute(h_gemm<0,1>, cudaFuncAttributeMaxDynamicSharedMemorySize, gemm_smem);
    cudaFuncSetAttribute(h_gemm<1,0>, cudaFuncAttributeMaxDynamicSharedMemorySize, gemm_smem);
    cudaFuncSetAttribute(h_gemm<2,1>, cudaFuncAttributeMaxDynamicSharedMemorySize, gemm_smem);
    cudaFuncSetAttribute(h_gemm<3,0>, cudaFuncAttributeMaxDynamicSharedMemorySize, gemm_smem);
    cudaFuncSetAttribute(attn_f16_kernel, cudaFuncAttributeMaxDynamicSharedMemorySize, ATT_SMEM_B);

    dim3 tb(32, 8);

    // weight transposes [K,N] -> fp16 [N,K]
    transpose_f16_kernel<C_,   3*INNER><<<dim3((3*INNER)/32, C_/32), tb>>>(w_qkv, p_wqkvT);
    transpose_f16_kernel<INNER, C_    ><<<dim3(C_/32, INNER/32), tb>>>(w_out, p_woutT);
    transpose_f16_kernel<C_,    HID   ><<<dim3(HID/32, C_/32), tb>>>(w_ff1, p_wff1T);
    transpose_f16_kernel<HID,   C_    ><<<dim3(C_/32, HID/32), tb>>>(w_ff2, p_wff2T);

    // 1. x [B, C, n] -> t [B, n, C]
    transpose_kernel<C_, N_><<<dim3(N_/32, C_/32, B_), tb>>>(x, p_t);

    // 2. dual layernorm -> fp16 a/f
    ln_dual_kernel<<<NT, 128>>>(ln1_g, ln1_b, ln2_g, ln2_b);

    // 3. qkv = a @ w_qkv  (fp16 out)
    h_gemm<0,1><<<dim3((3*INNER)/128, NT/128), 128, gemm_smem>>>(
        p_a16, p_wqkvT, p_qkv16, NT, 3*INNER, C_, nullptr, nullptr, nullptr);

    // 4. attention (full fp16 tensor-core, register P)
    attn_f16_kernel<<<B_ * HEADS, 256, ATT_SMEM_B>>>(btab);

    // 5. attn_out = o @ w_out + b_out  (fp32 out)
    h_gemm<1,0><<<dim3(C_/128, NT/128), 128, gemm_smem>>>(
        p_o16, p_woutT, p_attn, NT, C_, INNER, b_out, nullptr, nullptr);

    // 6. h = gelu(f @ w_ff1 + b_ff1)  (fp16 out)
    h_gemm<2,1><<<dim3(HID/128, NT/128), 128, gemm_smem>>>(
        p_f16, p_wff1T, p_h16, NT, HID, C_, b_ff1, nullptr, nullptr);

    // 7. y = h @ w_ff2 + b_ff2 + t + attn_out  (fp32 out)
    h_gemm<3,0><<<dim3(C_/128, NT/128), 128, gemm_smem>>>(
        p_h16, p_wff2T, p_y, NT, C_, HID, b_ff2, p_t, p_attn);

    // 8. y [B, n, C] -> out [B, C, n]
    transpose_kernel<N_, C_><<<dim3(C_/32, N_/32, B_), tb>>>(p_y, out);
}